// round 12
// baseline (speedup 1.0000x reference)
#include <cuda_runtime.h>
#include <cuda_fp16.h>
#include <math.h>
#include <stdint.h>

// ---------------- problem constants ----------------
#define NFEAT   256
#define NHID    128
#define NHEAD   4
#define NHEADL  6
#define NCLASS  40
#define HIDDIM  (NHID*NHEAD)      // 512
#define MAXN    10000
#define MAXE    160000
#define MAXEDGE (MAXE + MAXN)
#define NEG_SLOPE 0.2f

// BT arena row offsets (halves)
#define OFF0 0                         // L0: 1032 rows x K=256
#define OFF1 264192                    // L1: 520 rows x K=512
#define OFF2 530432                    // L2: 292 rows x K=512
#define BT_TOTAL 679936

// ---------------- scratch (static device memory) ----------------
__device__ float g_XW [MAXN * HIDDIM];
__device__ float g_X1 [MAXN * HIDDIM];
__device__ float g_X2 [MAXN * HIDDIM];
__device__ float g_SKIP[MAXN * HIDDIM];
__device__ float g_ASRC[MAXN * NHEADL];
__device__ float g_ADST[MAXN * NHEADL];
__device__ __half g_AH[MAXN * HIDDIM];
__device__ __half g_AL[MAXN * HIDDIM];
__device__ __half g_BT[BT_TOTAL];
__device__ int   g_rowptr[MAXN + 1];
__device__ int   g_deg [2 * MAXN];     // [0,MAXN): degree, [MAXN,2MAXN): scatter counters
__device__ int   g_csrsrc[MAXEDGE];
__device__ int   g_is64;

// ---------------- edge dtype detection ----------------
__global__ void detect_i64_kernel(const int* w) {
    if (threadIdx.x == 0) {
        int all0 = 1;
        #pragma unroll
        for (int i = 0; i < 64; i++) if (w[2*i + 1] != 0) all0 = 0;
        g_is64 = all0;
    }
}

__device__ __forceinline__ int edge_at(const void* ei, long long idx) {
    if (g_is64) return (int)((const long long*)ei)[idx];
    return ((const int*)ei)[idx];
}

// scan + self-loop placement fused (csrsrc[rowptr[n+1]-1] = n)
__global__ void scan_kernel(int n) {
    const int CH = (n + 1023) >> 10;
    int t = threadIdx.x;
    int local[16];
    int base = t * CH;
    int run = 0;
    #pragma unroll
    for (int j = 0; j < 16; j++) {
        if (j >= CH) break;
        int idx = base + j;
        int v = (idx < n) ? (g_deg[idx] + 1) : 0;
        run += v;
        local[j] = run;
    }
    int lane = t & 31, wid = t >> 5;
    int x = run;
    #pragma unroll
    for (int o = 1; o < 32; o <<= 1) {
        int y = __shfl_up_sync(0xFFFFFFFFu, x, o);
        if (lane >= o) x += y;
    }
    __shared__ int wsum[32];
    if (lane == 31) wsum[wid] = x;
    __syncthreads();
    if (wid == 0) {
        int w = wsum[lane];
        #pragma unroll
        for (int o = 1; o < 32; o <<= 1) {
            int y = __shfl_up_sync(0xFFFFFFFFu, w, o);
            if (lane >= o) w += y;
        }
        wsum[lane] = w;
    }
    __syncthreads();
    int excl = x - run + (wid > 0 ? wsum[wid - 1] : 0);
    if (t == 0) g_rowptr[0] = 0;
    #pragma unroll
    for (int j = 0; j < 16; j++) {
        if (j >= CH) break;
        int idx = base + j;
        if (idx < n) {
            int rp = excl + local[j];
            g_rowptr[idx + 1] = rp;
            g_csrsrc[rp - 1] = idx;          // self loop in last slot
        }
    }
}

__global__ void scatter_kernel(const void* ei, int E) {
    int e = blockIdx.x * blockDim.x + threadIdx.x;
    if (e < E) {
        int d = edge_at(ei, (long long)E + e);
        int s = edge_at(ei, e);
        int p = g_rowptr[d] + atomicAdd(&g_deg[MAXN + d], 1);
        g_csrsrc[p] = s;
    }
}

// ---------------- fused preprocessing: watt + transpose + A-split + degree in ONE grid ----------------
// blocks [0,1536): watt ; [1536,2208): transposes ; [2208, 2208+splitBlk): x split ; rest: degree
__global__ void prep_kernel(const float* __restrict__ x, int Nx, int splitBlk,
                            const void* __restrict__ ei, int E,
                            const float* __restrict__ W0, const float* __restrict__ Wsi,
                            const float* __restrict__ W1, const float* __restrict__ W2,
                            const float* __restrict__ Wso,
                            const float* __restrict__ as0, const float* __restrict__ ad0,
                            const float* __restrict__ as1, const float* __restrict__ ad1,
                            const float* __restrict__ as2, const float* __restrict__ ad2,
                            __half* __restrict__ AH, __half* __restrict__ AL,
                            __half* __restrict__ BT) {
    __shared__ float t[32][33];
    int b = blockIdx.x;
    int tid = threadIdx.x;
    if (b < 1536) {
        // ---- watt: one (k, j) dot per warp ----
        int gw = b * 8 + (tid >> 5);
        int lane = tid & 31;
        const float *W, *att; int K, C, k, j, attRow, Ww; __half* dst;
        if (gw < 2048)       { int q = gw;        k = q >> 3; j = q & 7;  W = W0; att = (j & 1) ? ad0 : as0; K = 256; C = 128; Ww = 512; attRow = 1024; dst = BT + OFF0; }
        else if (gw < 6144)  { int q = gw - 2048; k = q >> 3; j = q & 7;  W = W1; att = (j & 1) ? ad1 : as1; K = 512; C = 128; Ww = 512; attRow = 512;  dst = BT + OFF1; }
        else                 { int q = gw - 6144; k = q / 12; j = q % 12; W = W2; att = (j & 1) ? ad2 : as2; K = 512; C = 40;  Ww = 240; attRow = 280;  dst = BT + OFF2; }
        int h = j >> 1;
        float s = 0.f;
        for (int c = lane; c < C; c += 32)
            s = fmaf(W[(size_t)k * Ww + h * C + c], att[h * C + c], s);
        #pragma unroll
        for (int o = 16; o; o >>= 1) s += __shfl_xor_sync(0xFFFFFFFFu, s, o);
        if (lane == 0) dst[(size_t)(attRow + j) * K + k] = __float2half(s);
    } else if (b < 2208) {
        // ---- weight transpose ----
        int bb = b - 1536;
        const float* src; int K, Ncol, rowOff, tile, ntx; __half* dst;
        if (bb < 128)      { src = W0;  K = 256; Ncol = 512; rowOff = 0;   dst = BT + OFF0; tile = bb;       ntx = 16; }
        else if (bb < 256) { src = Wsi; K = 256; Ncol = 512; rowOff = 512; dst = BT + OFF0; tile = bb - 128; ntx = 16; }
        else if (bb < 512) { src = W1;  K = 512; Ncol = 512; rowOff = 0;   dst = BT + OFF1; tile = bb - 256; ntx = 16; }
        else if (bb < 640) { src = W2;  K = 512; Ncol = 240; rowOff = 0;   dst = BT + OFF2; tile = bb - 512; ntx = 8;  }
        else               { src = Wso; K = 512; Ncol = 40;  rowOff = 240; dst = BT + OFF2; tile = bb - 640; ntx = 2;  }
        int kb = (tile / ntx) * 32, nb = (tile % ntx) * 32;
        int tx = tid & 31, ty = tid >> 5;
        #pragma unroll
        for (int j = ty; j < 32; j += 8) {
            int k = kb + j, n = nb + tx;
            t[j][tx] = (k < K && n < Ncol) ? src[(size_t)k * Ncol + n] : 0.f;
        }
        __syncthreads();
        #pragma unroll
        for (int j = ty; j < 32; j += 8) {
            int n = nb + j, k = kb + tx;
            if (n < Ncol && k < K)
                dst[(size_t)(n + rowOff) * K + k] = __float2half(t[tx][j]);
        }
    } else if (b < 2208 + splitBlk) {
        // ---- x -> split fp16 ----
        int i = (b - 2208) * 256 + tid;
        if (i < Nx) {
            float v = x[i];
            __half h = __float2half(v);
            AH[i] = h;
            AL[i] = __float2half(v - __half2float(h));
        }
    } else {
        // ---- degree histogram ----
        int e = (b - 2208 - splitBlk) * 256 + tid;
        if (e < E) atomicAdd(&g_deg[edge_at(ei, (long long)E + e)], 1);
    }
}

// ---------------- split-fp16 tensor-core GEMM, 3-stage pipeline ----------------
#define GBM 128
#define GBN 64
#define GBK 32
#define APADB 80
#define ABYTES (GBM*APADB)
#define BBYTES (GBN*APADB)
#define STAGEB (2*ABYTES + BBYTES)
#define NSTAGE 3
#define SMEM_GEMM (NSTAGE*STAGEB)

__device__ __forceinline__ void cp16(uint32_t dst, const void* src) {
    asm volatile("cp.async.cg.shared.global [%0], [%1], 16;\n" :: "r"(dst), "l"(src));
}

__device__ __forceinline__ void ldsm4(uint32_t* r, uint32_t addr) {
    asm volatile("ldmatrix.sync.aligned.m8n8.x4.shared.b16 {%0,%1,%2,%3}, [%4];"
                 : "=r"(r[0]), "=r"(r[1]), "=r"(r[2]), "=r"(r[3]) : "r"(addr));
}

__device__ __forceinline__ void mma16816(float* c, const uint32_t* a, const uint32_t* b) {
    asm volatile("mma.sync.aligned.m16n8k16.row.col.f32.f16.f16.f32 "
                 "{%0,%1,%2,%3}, {%4,%5,%6,%7}, {%8,%9}, {%0,%1,%2,%3};"
                 : "+f"(c[0]), "+f"(c[1]), "+f"(c[2]), "+f"(c[3])
                 : "r"(a[0]), "r"(a[1]), "r"(a[2]), "r"(a[3]), "r"(b[0]), "r"(b[1]));
}

__global__ void __launch_bounds__(256, 2)
gemm_split_f16(const __half* __restrict__ AH, const __half* __restrict__ AL,
               const __half* __restrict__ BT,
               const float* __restrict__ bias2,
               float* __restrict__ C, float* __restrict__ C2,
               float* __restrict__ ASRC, float* __restrict__ ADST,
               int split1, int split2, int Hatt,
               int M, int K, int Ntot) {
    extern __shared__ char smem[];
    uint32_t sbase = (uint32_t)__cvta_generic_to_shared(smem);
    int tid = threadIdx.x, lane = tid & 31, warp = tid >> 5;
    int bm = blockIdx.y * GBM, bn = blockIdx.x * GBN;
    int m0 = (warp >> 1) * 32, n0 = (warp & 1) * 32;
    int nIter = K / GBK;

    float acc[2][4][4] = {};

    auto stage_load = [&](int it, int s) {
        int k0 = it * GBK;
        uint32_t sb = sbase + s * STAGEB;
        #pragma unroll
        for (int rep = 0; rep < 2; rep++) {
            int idx = tid + rep * 256;
            int r = idx >> 2, ch = idx & 3;
            int ra = bm + r; if (ra >= M) ra = M - 1;
            size_t off = (size_t)ra * K + k0 + ch * 8;
            cp16(sb + r * APADB + ch * 16, AH + off);
            cp16(sb + ABYTES + r * APADB + ch * 16, AL + off);
        }
        {
            int r = tid >> 2, ch = tid & 3;
            int ra = bn + r; if (ra >= Ntot) ra = Ntot - 1;
            size_t off = (size_t)ra * K + k0 + ch * 8;
            cp16(sb + 2 * ABYTES + r * APADB + ch * 16, BT + off);
        }
    };

    int aRow = lane & 15;
    int aKby = (lane >> 4) * 16;
    int bRow = (lane & 7) + ((lane >> 4) << 3);
    int bKby = ((lane >> 3) & 1) * 16;

    stage_load(0, 0);
    asm volatile("cp.async.commit_group;\n");
    if (nIter > 1) stage_load(1, 1);
    asm volatile("cp.async.commit_group;\n");

    for (int it = 0; it < nIter; it++) {
        int s = it % NSTAGE;
        asm volatile("cp.async.wait_group 1;\n");
        __syncthreads();
        if (it + 2 < nIter) stage_load(it + 2, (it + 2) % NSTAGE);
        asm volatile("cp.async.commit_group;\n");

        uint32_t sb  = sbase + s * STAGEB;
        uint32_t pAH = sb + (m0 + aRow) * APADB + aKby;
        uint32_t pAL = pAH + ABYTES;
        uint32_t pB  = sb + 2 * ABYTES + (n0 + bRow) * APADB + bKby;

        #pragma unroll
        for (int ks = 0; ks < 2; ks++) {
            int kb = ks * 32;
            uint32_t ah[2][4], al[2][4];
            ldsm4(ah[0], pAH + kb);
            ldsm4(ah[1], pAH + 16 * APADB + kb);
            ldsm4(al[0], pAL + kb);
            ldsm4(al[1], pAL + 16 * APADB + kb);
            uint32_t b01[4], b23[4];
            ldsm4(b01, pB + kb);
            ldsm4(b23, pB + 16 * APADB + kb);
            const uint32_t* bf[4] = {b01, b01 + 2, b23, b23 + 2};
            #pragma unroll
            for (int mt = 0; mt < 2; mt++)
                #pragma unroll
                for (int nt = 0; nt < 4; nt++) mma16816(acc[mt][nt], ah[mt], bf[nt]);
            #pragma unroll
            for (int mt = 0; mt < 2; mt++)
                #pragma unroll
                for (int nt = 0; nt < 4; nt++) mma16816(acc[mt][nt], al[mt], bf[nt]);
        }
        __syncthreads();
    }

    int attEnd = split2 + 2 * Hatt;
    #pragma unroll
    for (int mt = 0; mt < 2; mt++) {
        #pragma unroll
        for (int nt = 0; nt < 4; nt++) {
            int r = bm + m0 + mt * 16 + (lane >> 2);
            int c = bn + n0 + nt * 8 + (lane & 3) * 2;
            #pragma unroll
            for (int half = 0; half < 2; half++) {
                int rr = r + half * 8;
                if (rr >= M) continue;
                #pragma unroll
                for (int j = 0; j < 2; j++) {
                    int cc = c + j;
                    float v = acc[mt][nt][half * 2 + j];
                    if (cc < split1) {
                        C[(size_t)rr * split1 + cc] = v;
                    } else if (cc < split2) {
                        int c2 = cc - split1;
                        if (bias2) v += bias2[c2];
                        C2[(size_t)rr * (split2 - split1) + c2] = v;
                    } else if (cc < attEnd) {
                        int ca = cc - split2;
                        int h = ca >> 1;
                        ((ca & 1) ? ADST : ASRC)[(size_t)rr * Hatt + h] = v;
                    }
                }
            }
        }
    }
}

__device__ __forceinline__ float lrelu(float x) { return x > 0.f ? x : NEG_SLOPE * x; }
__device__ __forceinline__ float eluf(float x)  { return x > 0.f ? x : expm1f(x); }

// ---------------- GAT aggregation: warp per (node, head-pair), prefetch pipeline ----------------
__global__ void gat_agg_concat4(const float* __restrict__ xw,
                                const float* __restrict__ asrc, const float* __restrict__ adst,
                                const float* __restrict__ bias, const float* __restrict__ skip,
                                float* __restrict__ out,
                                __half* __restrict__ oh, __half* __restrict__ ol,
                                int N) {
    int gw = (blockIdx.x * blockDim.x + threadIdx.x) >> 5;
    if (gw >= 2 * N) return;
    int n = gw >> 1, hp = gw & 1;            // heads 2hp, 2hp+1
    int lane = threadIdx.x & 31;
    int s0 = g_rowptr[n], s1 = g_rowptr[n + 1];
    float2 ad = *(const float2*)(adst + n * 4 + hp * 2);

    float2 m = make_float2(-1e30f, -1e30f);
    for (int i = s0 + lane; i < s1; i += 32) {
        int s = g_csrsrc[i];
        float2 as = *(const float2*)(asrc + s * 4 + hp * 2);
        m.x = fmaxf(m.x, lrelu(as.x + ad.x));
        m.y = fmaxf(m.y, lrelu(as.y + ad.y));
    }
    #pragma unroll
    for (int o = 16; o; o >>= 1) {
        m.x = fmaxf(m.x, __shfl_xor_sync(0xFFFFFFFFu, m.x, o));
        m.y = fmaxf(m.y, __shfl_xor_sync(0xFFFFFFFFu, m.y, o));
    }

    float4 acc0 = {0,0,0,0}, acc1 = {0,0,0,0};
    float2 den = make_float2(0.f, 0.f);
    const size_t rowOff = (size_t)hp * (2 * NHID);

    float2 asC = {0,0}; float4 v0c = {0,0,0,0}, v1c = {0,0,0,0};
    if (s0 < s1) {
        int s = g_csrsrc[s0];
        asC = *(const float2*)(asrc + s * 4 + hp * 2);
        const float4* row = (const float4*)(xw + (size_t)s * HIDDIM + rowOff);
        v0c = row[lane]; v1c = row[32 + lane];
    }
    for (int i = s0; i < s1; i++) {
        float2 asN = {0,0}; float4 v0n = {0,0,0,0}, v1n = {0,0,0,0};
        if (i + 1 < s1) {
            int s = g_csrsrc[i + 1];
            asN = *(const float2*)(asrc + s * 4 + hp * 2);
            const float4* row = (const float4*)(xw + (size_t)s * HIDDIM + rowOff);
            v0n = row[lane]; v1n = row[32 + lane];
        }
        float w0 = __expf(lrelu(asC.x + ad.x) - m.x);
        float w1 = __expf(lrelu(asC.y + ad.y) - m.y);
        den.x += w0; den.y += w1;
        acc0.x = fmaf(w0, v0c.x, acc0.x); acc0.y = fmaf(w0, v0c.y, acc0.y);
        acc0.z = fmaf(w0, v0c.z, acc0.z); acc0.w = fmaf(w0, v0c.w, acc0.w);
        acc1.x = fmaf(w1, v1c.x, acc1.x); acc1.y = fmaf(w1, v1c.y, acc1.y);
        acc1.z = fmaf(w1, v1c.z, acc1.z); acc1.w = fmaf(w1, v1c.w, acc1.w);
        asC = asN; v0c = v0n; v1c = v1n;
    }
    float invs[2] = {1.f / (den.x + 1e-16f), 1.f / (den.y + 1e-16f)};
    float4 accs[2] = {acc0, acc1};
    #pragma unroll
    for (int h = 0; h < 2; h++) {
        int ch = (hp * 2 + h) * NHID + lane * 4;
        int base = n * HIDDIM + ch;
        float4 bv = *(const float4*)(bias + ch);
        float4 sv = *(const float4*)(skip + base);
        float4 o;
        o.x = eluf(accs[h].x * invs[h] + bv.x + sv.x);
        o.y = eluf(accs[h].y * invs[h] + bv.y + sv.y);
        o.z = eluf(accs[h].z * invs[h] + bv.z + sv.z);
        o.w = eluf(accs[h].w * invs[h] + bv.w + sv.w);
        *(float4*)(out + base) = o;
        __half hx = __float2half(o.x), hy = __float2half(o.y);
        __half hz = __float2half(o.z), hw = __float2half(o.w);
        __half2* ph = (__half2*)(oh + base);
        __half2* pl = (__half2*)(ol + base);
        ph[0] = __halves2half2(hx, hy);
        ph[1] = __halves2half2(hz, hw);
        pl[0] = __halves2half2(__float2half(o.x - __half2float(hx)),
                               __float2half(o.y - __half2float(hy)));
        pl[1] = __halves2half2(__float2half(o.z - __half2float(hz)),
                               __float2half(o.w - __half2float(hw)));
    }
}

// ---------------- final layer: warp per node, 6 heads, lane-parallel max, pipelined ----------------
__global__ void gat_agg_mean6(const float* __restrict__ xw,
                              const float* __restrict__ asrc, const float* __restrict__ adst,
                              float* __restrict__ out, int N) {
    int n = (blockIdx.x * blockDim.x + threadIdx.x) >> 5;
    if (n >= N) return;
    int lane = threadIdx.x & 31;
    bool act = lane < 30;
    int h = act ? (lane / 5) : 5;
    int p = act ? (lane - h * 5) : 0;
    int s0 = g_rowptr[n], s1 = g_rowptr[n + 1];

    float mloc = -1e30f;
    int h2 = act ? (lane % 6) : 0;
    float ad2 = adst[n * NHEADL + h2];
    if (act) {
        for (int i = s0 + lane / 6; i < s1; i += 5) {
            int s = g_csrsrc[i];
            mloc = fmaxf(mloc, lrelu(asrc[s * NHEADL + h2] + ad2));
        }
    }
    #pragma unroll
    for (int off = 6; off <= 24; off <<= 1) {
        int src = lane + off; if (src >= 30) src -= 30;
        float t = __shfl_sync(0xFFFFFFFFu, mloc, src);
        mloc = fmaxf(mloc, t);
    }
    float m  = __shfl_sync(0xFFFFFFFFu, mloc, h);
    float ad = adst[n * NHEADL + h];

    float4 acc0 = {0,0,0,0}, acc1 = {0,0,0,0};
    float den = 0.f;

    float aC = 0.f; float4 v0c = {0,0,0,0}, v1c = {0,0,0,0};
    if (s0 < s1) {
        int s = g_csrsrc[s0];
        aC = asrc[s * NHEADL + h];
        if (act) {
            const float4* row = (const float4*)(xw + (size_t)s * (NHEADL * NCLASS)) + h * 10;
            v0c = row[p]; v1c = row[p + 5];
        }
    }
    for (int i = s0; i < s1; i++) {
        float aN = 0.f; float4 v0n = {0,0,0,0}, v1n = {0,0,0,0};
        if (i + 1 < s1) {
            int s = g_csrsrc[i + 1];
            aN = asrc[s * NHEADL + h];
            if (act) {
                const float4* row = (const float4*)(xw + (size_t)s * (NHEADL * NCLASS)) + h * 10;
                v0n = row[p]; v1n = row[p + 5];
            }
        }
        float w = __expf(lrelu(aC + ad) - m);
        den += w;
        acc0.x = fmaf(w, v0c.x, acc0.x); acc0.y = fmaf(w, v0c.y, acc0.y);
        acc0.z = fmaf(w, v0c.z, acc0.z); acc0.w = fmaf(w, v0c.w, acc0.w);
        acc1.x = fmaf(w, v1c.x, acc1.x); acc1.y = fmaf(w, v1c.y, acc1.y);
        acc1.z = fmaf(w, v1c.z, acc1.z); acc1.w = fmaf(w, v1c.w, acc1.w);
        aC = aN; v0c = v0n; v1c = v1n;
    }
    float sc = act ? (1.f / (den + 1e-16f)) * (1.f / (float)NHEADL) : 0.f;
    acc0.x *= sc; acc0.y *= sc; acc0.z *= sc; acc0.w *= sc;
    acc1.x *= sc; acc1.y *= sc; acc1.z *= sc; acc1.w *= sc;

    #define SHF4(d, v, src) \
        d.x = __shfl_sync(0xFFFFFFFFu, v.x, src); \
        d.y = __shfl_sync(0xFFFFFFFFu, v.y, src); \
        d.z = __shfl_sync(0xFFFFFFFFu, v.z, src); \
        d.w = __shfl_sync(0xFFFFFFFFu, v.w, src);
    float4 t;
    SHF4(t, acc0, (lane + 15) & 31);
    acc0.x += t.x; acc0.y += t.y; acc0.z += t.z; acc0.w += t.w;
    SHF4(t, acc1, (lane + 15) & 31);
    acc1.x += t.x; acc1.y += t.y; acc1.z += t.z; acc1.w += t.w;
    float4 a5, a10, b5, b10;
    SHF4(a5,  acc0, (lane + 5) & 31);
    SHF4(a10, acc0, (lane + 10) & 31);
    SHF4(b5,  acc1, (lane + 5) & 31);
    SHF4(b10, acc1, (lane + 10) & 31);
    if (lane < 5) {
        float4* o = (float4*)(out + (size_t)n * NCLASS);
        float4 c0 = o[lane];
        float4 c1 = o[lane + 5];
        c0.x += acc0.x + a5.x + a10.x; c0.y += acc0.y + a5.y + a10.y;
        c0.z += acc0.z + a5.z + a10.z; c0.w += acc0.w + a5.w + a10.w;
        c1.x += acc1.x + b5.x + b10.x; c1.y += acc1.y + b5.y + b10.y;
        c1.z += acc1.z + b5.z + b10.z; c1.w += acc1.w + b5.w + b10.w;
        o[lane] = c0;
        o[lane + 5] = c1;
    }
    #undef SHF4
}

// ---------------- launch ----------------
extern "C" void kernel_launch(void* const* d_in, const int* in_sizes, int n_in,
                              void* d_out, int out_size) {
    const float* x        = (const float*)d_in[0];
    const void*  ei       = d_in[1];
    const float* W0       = (const float*)d_in[2];
    const float* a_src0   = (const float*)d_in[3];
    const float* a_dst0   = (const float*)d_in[4];
    const float* b0       = (const float*)d_in[5];
    const float* Wskip_in = (const float*)d_in[6];
    const float* W1       = (const float*)d_in[7];
    const float* a_src1   = (const float*)d_in[8];
    const float* a_dst1   = (const float*)d_in[9];
    const float* b1       = (const float*)d_in[10];
    const float* W2       = (const float*)d_in[11];
    const float* a_src2   = (const float*)d_in[12];
    const float* a_dst2   = (const float*)d_in[13];
    const float* b2       = (const float*)d_in[14];
    const float* Wskip_out= (const float*)d_in[15];
    float* out = (float*)d_out;

    int N = in_sizes[0] / NFEAT;
    int E = in_sizes[1] / 2;

    float *XW, *X1, *X2, *SKIP, *ASRC, *ADST;
    __half *AH, *AL, *BT;
    int *deg;
    cudaGetSymbolAddress((void**)&XW,   g_XW);
    cudaGetSymbolAddress((void**)&X1,   g_X1);
    cudaGetSymbolAddress((void**)&X2,   g_X2);
    cudaGetSymbolAddress((void**)&SKIP, g_SKIP);
    cudaGetSymbolAddress((void**)&ASRC, g_ASRC);
    cudaGetSymbolAddress((void**)&ADST, g_ADST);
    cudaGetSymbolAddress((void**)&AH,   g_AH);
    cudaGetSymbolAddress((void**)&AL,   g_AL);
    cudaGetSymbolAddress((void**)&BT,   g_BT);
    cudaGetSymbolAddress((void**)&deg,  g_deg);

    cudaFuncSetAttribute(gemm_split_f16, cudaFuncAttributeMaxDynamicSharedMemorySize, SMEM_GEMM);

    cudaMemsetAsync(deg, 0, 2 * MAXN * sizeof(int));
    detect_i64_kernel<<<1, 32>>>((const int*)ei);

    dim3 blk(256);
    auto cdiv = [](int a, int b) { return (a + b - 1) / b; };
    auto ggrid = [&](int Ncol) { return dim3(cdiv(Ncol, GBN), cdiv(N, GBM)); };

    int gridN  = cdiv(N * 32, 256);
    int gridN2 = cdiv(N * 2 * 32, 256);
    int Nx = N * NFEAT;
    int splitBlk = cdiv(Nx, 256);

    // ---- fused preprocessing (watt + transposes + split + degree) ----
    prep_kernel<<<2208 + splitBlk + cdiv(E, 256), blk>>>(
        x, Nx, splitBlk, ei, E, W0, Wskip_in, W1, W2, Wskip_out,
        a_src0, a_dst0, a_src1, a_dst1, a_src2, a_dst2,
        AH, AL, BT);

    // ---- layer 0 GEMM: x @ [W0 | Wskip_in | Watt0] -> XW, SKIP, ASRC/ADST ----
    gemm_split_f16<<<ggrid(1032), blk, SMEM_GEMM>>>(
        AH, AL, BT + OFF0, nullptr, XW, SKIP, ASRC, ADST,
        HIDDIM, 2 * HIDDIM, NHEAD, N, NFEAT, 1032);

    // ---- CSR finalize ----
    scan_kernel<<<1, 1024>>>(N);
    scatter_kernel<<<cdiv(E, 256), blk>>>(ei, E);

    gat_agg_concat4<<<gridN2, blk>>>(XW, ASRC, ADST, b0, SKIP, X1, AH, AL, N);

    // ---- layer 1: x1 @ [W1 | Watt1] ----
    gemm_split_f16<<<ggrid(520), blk, SMEM_GEMM>>>(
        AH, AL, BT + OFF1, nullptr, XW, XW, ASRC, ADST,
        HIDDIM, HIDDIM, NHEAD, N, HIDDIM, 520);
    gat_agg_concat4<<<gridN2, blk>>>(XW, ASRC, ADST, b1, X1, X2, AH, AL, N);

    // ---- layer 2: x2 @ [W2 | Wskip_out | Watt2] ----
    gemm_split_f16<<<ggrid(292), blk, SMEM_GEMM>>>(
        AH, AL, BT + OFF2, b2, XW, out, ASRC, ADST,
        NHEADL * NCLASS, NHEADL * NCLASS + NCLASS, NHEADL, N, HIDDIM, 292);
    gat_agg_mean6<<<gridN, blk>>>(XW, ASRC, ADST, out, N);
}

// round 13
// speedup vs baseline: 1.0942x; 1.0942x over previous
#include <cuda_runtime.h>
#include <cuda_fp16.h>
#include <math.h>
#include <stdint.h>

// ---------------- problem constants ----------------
#define NFEAT   256
#define NHID    128
#define NHEAD   4
#define NHEADL  6
#define NCLASS  40
#define HIDDIM  (NHID*NHEAD)      // 512
#define MAXN    10000
#define MAXE    160000
#define MAXEDGE (MAXE + MAXN)
#define NEG_SLOPE 0.2f

// BT arena row offsets (halves)
#define OFF0 0
#define OFF1 264192
#define OFF2 530432
#define BT_TOTAL 679936

// ---------------- scratch (static device memory) ----------------
__device__ float g_XW [MAXN * HIDDIM];
__device__ float g_X1 [MAXN * HIDDIM];
__device__ float g_X2 [MAXN * HIDDIM];
__device__ float g_SKIP[MAXN * HIDDIM];
__device__ float g_ASRC[MAXN * NHEADL];
__device__ float g_ADST[MAXN * NHEADL];
__device__ __half g_AH[MAXN * HIDDIM];
__device__ __half g_AL[MAXN * HIDDIM];
__device__ __half g_BT[BT_TOTAL];
__device__ int   g_rowptr[MAXN + 1];
__device__ int   g_deg [2 * MAXN];
__device__ int   g_csrsrc[MAXEDGE];
__device__ int   g_is64;

// ---------------- edge dtype detection ----------------
__global__ void detect_i64_kernel(const int* w) {
    if (threadIdx.x == 0) {
        int all0 = 1;
        #pragma unroll
        for (int i = 0; i < 64; i++) if (w[2*i + 1] != 0) all0 = 0;
        g_is64 = all0;
    }
}

__device__ __forceinline__ int edge_at(const void* ei, long long idx) {
    if (g_is64) return (int)((const long long*)ei)[idx];
    return ((const int*)ei)[idx];
}

// scan + self-loop placement fused; batched predicated loads (no serializing break)
__global__ void scan_kernel(int n) {
    const int CH = (n + 1023) >> 10;    // <=16
    int t = threadIdx.x;
    int base = t * CH;
    int vals[16];
    #pragma unroll
    for (int j = 0; j < 16; j++) {
        int idx = base + j;
        vals[j] = (j < CH && idx < n) ? (g_deg[idx] + 1) : 0;
    }
    int local[16];
    int run = 0;
    #pragma unroll
    for (int j = 0; j < 16; j++) { run += vals[j]; local[j] = run; }
    int lane = t & 31, wid = t >> 5;
    int x = run;
    #pragma unroll
    for (int o = 1; o < 32; o <<= 1) {
        int y = __shfl_up_sync(0xFFFFFFFFu, x, o);
        if (lane >= o) x += y;
    }
    __shared__ int wsum[32];
    if (lane == 31) wsum[wid] = x;
    __syncthreads();
    if (wid == 0) {
        int w = wsum[lane];
        #pragma unroll
        for (int o = 1; o < 32; o <<= 1) {
            int y = __shfl_up_sync(0xFFFFFFFFu, w, o);
            if (lane >= o) w += y;
        }
        wsum[lane] = w;
    }
    __syncthreads();
    int excl = x - run + (wid > 0 ? wsum[wid - 1] : 0);
    if (t == 0) g_rowptr[0] = 0;
    #pragma unroll
    for (int j = 0; j < 16; j++) {
        int idx = base + j;
        if (j < CH && idx < n) {
            int rp = excl + local[j];
            g_rowptr[idx + 1] = rp;
            g_csrsrc[rp - 1] = idx;
        }
    }
}

__global__ void scatter_kernel(const void* ei, int E) {
    int e = blockIdx.x * blockDim.x + threadIdx.x;
    if (e < E) {
        int d = edge_at(ei, (long long)E + e);
        int s = edge_at(ei, e);
        int p = g_rowptr[d] + atomicAdd(&g_deg[MAXN + d], 1);
        g_csrsrc[p] = s;
    }
}

// ---------------- fused preprocessing: watt + transpose + A-split + degree ----------------
__global__ void prep_kernel(const float* __restrict__ x, int Nx, int splitBlk,
                            const void* __restrict__ ei, int E,
                            const float* __restrict__ W0, const float* __restrict__ Wsi,
                            const float* __restrict__ W1, const float* __restrict__ W2,
                            const float* __restrict__ Wso,
                            const float* __restrict__ as0, const float* __restrict__ ad0,
                            const float* __restrict__ as1, const float* __restrict__ ad1,
                            const float* __restrict__ as2, const float* __restrict__ ad2,
                            __half* __restrict__ AH, __half* __restrict__ AL,
                            __half* __restrict__ BT) {
    __shared__ float t[32][33];
    int b = blockIdx.x;
    int tid = threadIdx.x;
    if (b < 1536) {
        int gw = b * 8 + (tid >> 5);
        int lane = tid & 31;
        const float *W, *att; int K, C, k, j, attRow, Ww; __half* dst;
        if (gw < 2048)       { int q = gw;        k = q >> 3; j = q & 7;  W = W0; att = (j & 1) ? ad0 : as0; K = 256; C = 128; Ww = 512; attRow = 1024; dst = BT + OFF0; }
        else if (gw < 6144)  { int q = gw - 2048; k = q >> 3; j = q & 7;  W = W1; att = (j & 1) ? ad1 : as1; K = 512; C = 128; Ww = 512; attRow = 512;  dst = BT + OFF1; }
        else                 { int q = gw - 6144; k = q / 12; j = q % 12; W = W2; att = (j & 1) ? ad2 : as2; K = 512; C = 40;  Ww = 240; attRow = 280;  dst = BT + OFF2; }
        int h = j >> 1;
        float s = 0.f;
        for (int c = lane; c < C; c += 32)
            s = fmaf(W[(size_t)k * Ww + h * C + c], att[h * C + c], s);
        #pragma unroll
        for (int o = 16; o; o >>= 1) s += __shfl_xor_sync(0xFFFFFFFFu, s, o);
        if (lane == 0) dst[(size_t)(attRow + j) * K + k] = __float2half(s);
    } else if (b < 2208) {
        int bb = b - 1536;
        const float* src; int K, Ncol, rowOff, tile, ntx; __half* dst;
        if (bb < 128)      { src = W0;  K = 256; Ncol = 512; rowOff = 0;   dst = BT + OFF0; tile = bb;       ntx = 16; }
        else if (bb < 256) { src = Wsi; K = 256; Ncol = 512; rowOff = 512; dst = BT + OFF0; tile = bb - 128; ntx = 16; }
        else if (bb < 512) { src = W1;  K = 512; Ncol = 512; rowOff = 0;   dst = BT + OFF1; tile = bb - 256; ntx = 16; }
        else if (bb < 640) { src = W2;  K = 512; Ncol = 240; rowOff = 0;   dst = BT + OFF2; tile = bb - 512; ntx = 8;  }
        else               { src = Wso; K = 512; Ncol = 40;  rowOff = 240; dst = BT + OFF2; tile = bb - 640; ntx = 2;  }
        int kb = (tile / ntx) * 32, nb = (tile % ntx) * 32;
        int tx = tid & 31, ty = tid >> 5;
        #pragma unroll
        for (int j = ty; j < 32; j += 8) {
            int k = kb + j, n = nb + tx;
            t[j][tx] = (k < K && n < Ncol) ? src[(size_t)k * Ncol + n] : 0.f;
        }
        __syncthreads();
        #pragma unroll
        for (int j = ty; j < 32; j += 8) {
            int n = nb + j, k = kb + tx;
            if (n < Ncol && k < K)
                dst[(size_t)(n + rowOff) * K + k] = __float2half(t[tx][j]);
        }
    } else if (b < 2208 + splitBlk) {
        int i = (b - 2208) * 256 + tid;
        if (i < Nx) {
            float v = x[i];
            __half h = __float2half(v);
            AH[i] = h;
            AL[i] = __float2half(v - __half2float(h));
        }
    } else {
        int e = (b - 2208 - splitBlk) * 256 + tid;
        if (e < E) atomicAdd(&g_deg[edge_at(ei, (long long)E + e)], 1);
    }
}

// ---------------- split-fp16 tensor-core GEMM, 3-stage pipeline ----------------
#define GBM 128
#define GBN 64
#define GBK 32
#define APADB 80
#define ABYTES (GBM*APADB)
#define BBYTES (GBN*APADB)
#define STAGEB (2*ABYTES + BBYTES)
#define NSTAGE 3
#define SMEM_GEMM (NSTAGE*STAGEB)

__device__ __forceinline__ void cp16(uint32_t dst, const void* src) {
    asm volatile("cp.async.cg.shared.global [%0], [%1], 16;\n" :: "r"(dst), "l"(src));
}

__device__ __forceinline__ void ldsm4(uint32_t* r, uint32_t addr) {
    asm volatile("ldmatrix.sync.aligned.m8n8.x4.shared.b16 {%0,%1,%2,%3}, [%4];"
                 : "=r"(r[0]), "=r"(r[1]), "=r"(r[2]), "=r"(r[3]) : "r"(addr));
}

__device__ __forceinline__ void mma16816(float* c, const uint32_t* a, const uint32_t* b) {
    asm volatile("mma.sync.aligned.m16n8k16.row.col.f32.f16.f16.f32 "
                 "{%0,%1,%2,%3}, {%4,%5,%6,%7}, {%8,%9}, {%0,%1,%2,%3};"
                 : "+f"(c[0]), "+f"(c[1]), "+f"(c[2]), "+f"(c[3])
                 : "r"(a[0]), "r"(a[1]), "r"(a[2]), "r"(a[3]), "r"(b[0]), "r"(b[1]));
}

__global__ void __launch_bounds__(256, 2)
gemm_split_f16(const __half* __restrict__ AH, const __half* __restrict__ AL,
               const __half* __restrict__ BT,
               const float* __restrict__ bias2,
               float* __restrict__ C, float* __restrict__ C2,
               float* __restrict__ ASRC, float* __restrict__ ADST,
               int split1, int split2, int Hatt,
               int M, int K, int Ntot) {
    extern __shared__ char smem[];
    uint32_t sbase = (uint32_t)__cvta_generic_to_shared(smem);
    int tid = threadIdx.x, lane = tid & 31, warp = tid >> 5;
    int bm = blockIdx.y * GBM, bn = blockIdx.x * GBN;
    int m0 = (warp >> 1) * 32, n0 = (warp & 1) * 32;
    int nIter = K / GBK;

    float acc[2][4][4] = {};

    auto stage_load = [&](int it, int s) {
        int k0 = it * GBK;
        uint32_t sb = sbase + s * STAGEB;
        #pragma unroll
        for (int rep = 0; rep < 2; rep++) {
            int idx = tid + rep * 256;
            int r = idx >> 2, ch = idx & 3;
            int ra = bm + r; if (ra >= M) ra = M - 1;
            size_t off = (size_t)ra * K + k0 + ch * 8;
            cp16(sb + r * APADB + ch * 16, AH + off);
            cp16(sb + ABYTES + r * APADB + ch * 16, AL + off);
        }
        {
            int r = tid >> 2, ch = tid & 3;
            int ra = bn + r; if (ra >= Ntot) ra = Ntot - 1;
            size_t off = (size_t)ra * K + k0 + ch * 8;
            cp16(sb + 2 * ABYTES + r * APADB + ch * 16, BT + off);
        }
    };

    int aRow = lane & 15;
    int aKby = (lane >> 4) * 16;
    int bRow = (lane & 7) + ((lane >> 4) << 3);
    int bKby = ((lane >> 3) & 1) * 16;

    stage_load(0, 0);
    asm volatile("cp.async.commit_group;\n");
    if (nIter > 1) stage_load(1, 1);
    asm volatile("cp.async.commit_group;\n");

    for (int it = 0; it < nIter; it++) {
        int s = it % NSTAGE;
        asm volatile("cp.async.wait_group 1;\n");
        __syncthreads();
        if (it + 2 < nIter) stage_load(it + 2, (it + 2) % NSTAGE);
        asm volatile("cp.async.commit_group;\n");

        uint32_t sb  = sbase + s * STAGEB;
        uint32_t pAH = sb + (m0 + aRow) * APADB + aKby;
        uint32_t pAL = pAH + ABYTES;
        uint32_t pB  = sb + 2 * ABYTES + (n0 + bRow) * APADB + bKby;

        #pragma unroll
        for (int ks = 0; ks < 2; ks++) {
            int kb = ks * 32;
            uint32_t ah[2][4], al[2][4];
            ldsm4(ah[0], pAH + kb);
            ldsm4(ah[1], pAH + 16 * APADB + kb);
            ldsm4(al[0], pAL + kb);
            ldsm4(al[1], pAL + 16 * APADB + kb);
            uint32_t b01[4], b23[4];
            ldsm4(b01, pB + kb);
            ldsm4(b23, pB + 16 * APADB + kb);
            const uint32_t* bf[4] = {b01, b01 + 2, b23, b23 + 2};
            #pragma unroll
            for (int mt = 0; mt < 2; mt++)
                #pragma unroll
                for (int nt = 0; nt < 4; nt++) mma16816(acc[mt][nt], ah[mt], bf[nt]);
            #pragma unroll
            for (int mt = 0; mt < 2; mt++)
                #pragma unroll
                for (int nt = 0; nt < 4; nt++) mma16816(acc[mt][nt], al[mt], bf[nt]);
        }
        __syncthreads();
    }

    int attEnd = split2 + 2 * Hatt;
    #pragma unroll
    for (int mt = 0; mt < 2; mt++) {
        #pragma unroll
        for (int nt = 0; nt < 4; nt++) {
            int r = bm + m0 + mt * 16 + (lane >> 2);
            int c = bn + n0 + nt * 8 + (lane & 3) * 2;
            #pragma unroll
            for (int half = 0; half < 2; half++) {
                int rr = r + half * 8;
                if (rr >= M) continue;
                #pragma unroll
                for (int j = 0; j < 2; j++) {
                    int cc = c + j;
                    float v = acc[mt][nt][half * 2 + j];
                    if (cc < split1) {
                        C[(size_t)rr * split1 + cc] = v;
                    } else if (cc < split2) {
                        int c2 = cc - split1;
                        if (bias2) v += bias2[c2];
                        C2[(size_t)rr * (split2 - split1) + c2] = v;
                    } else if (cc < attEnd) {
                        int ca = cc - split2;
                        int h = ca >> 1;
                        ((ca & 1) ? ADST : ASRC)[(size_t)rr * Hatt + h] = v;
                    }
                }
            }
        }
    }
}

__device__ __forceinline__ float lrelu(float x) { return x > 0.f ? x : NEG_SLOPE * x; }
__device__ __forceinline__ float eluf(float x)  { return x > 0.f ? x : expm1f(x); }

// ---------------- GAT aggregation, warp per node, 4 heads, value-prefetch pipeline ----------------
__global__ void gat_agg_concat4(const float* __restrict__ xw,
                                const float* __restrict__ asrc, const float* __restrict__ adst,
                                const float* __restrict__ bias, const float* __restrict__ skip,
                                float* __restrict__ out,
                                __half* __restrict__ oh, __half* __restrict__ ol,
                                int N) {
    int n = (blockIdx.x * blockDim.x + threadIdx.x) >> 5;
    if (n >= N) return;
    int lane = threadIdx.x & 31;
    int s0 = g_rowptr[n], s1 = g_rowptr[n + 1];
    float4 ad = *(const float4*)(adst + n * 4);

    float4 m = make_float4(-1e30f, -1e30f, -1e30f, -1e30f);
    for (int i = s0 + lane; i < s1; i += 32) {
        int s = g_csrsrc[i];
        float4 as = *(const float4*)(asrc + s * 4);
        m.x = fmaxf(m.x, lrelu(as.x + ad.x));
        m.y = fmaxf(m.y, lrelu(as.y + ad.y));
        m.z = fmaxf(m.z, lrelu(as.z + ad.z));
        m.w = fmaxf(m.w, lrelu(as.w + ad.w));
    }
    #pragma unroll
    for (int o = 16; o; o >>= 1) {
        m.x = fmaxf(m.x, __shfl_xor_sync(0xFFFFFFFFu, m.x, o));
        m.y = fmaxf(m.y, __shfl_xor_sync(0xFFFFFFFFu, m.y, o));
        m.z = fmaxf(m.z, __shfl_xor_sync(0xFFFFFFFFu, m.z, o));
        m.w = fmaxf(m.w, __shfl_xor_sync(0xFFFFFFFFu, m.w, o));
    }

    float4 acc0 = {0,0,0,0}, acc1 = {0,0,0,0}, acc2 = {0,0,0,0}, acc3 = {0,0,0,0};
    float4 den = {0,0,0,0};

    float4 asC = {0,0,0,0}, v0c = {0,0,0,0}, v1c = {0,0,0,0}, v2c = {0,0,0,0}, v3c = {0,0,0,0};
    if (s0 < s1) {
        int s = g_csrsrc[s0];
        asC = *(const float4*)(asrc + s * 4);
        const float4* row = (const float4*)(xw + (size_t)s * HIDDIM);
        v0c = row[lane]; v1c = row[32 + lane]; v2c = row[64 + lane]; v3c = row[96 + lane];
    }
    for (int i = s0; i < s1; i++) {
        float4 asN = {0,0,0,0}, v0n = {0,0,0,0}, v1n = {0,0,0,0}, v2n = {0,0,0,0}, v3n = {0,0,0,0};
        if (i + 1 < s1) {
            int s = g_csrsrc[i + 1];
            asN = *(const float4*)(asrc + s * 4);
            const float4* row = (const float4*)(xw + (size_t)s * HIDDIM);
            v0n = row[lane]; v1n = row[32 + lane]; v2n = row[64 + lane]; v3n = row[96 + lane];
        }
        float w0 = __expf(lrelu(asC.x + ad.x) - m.x);
        float w1 = __expf(lrelu(asC.y + ad.y) - m.y);
        float w2 = __expf(lrelu(asC.z + ad.z) - m.z);
        float w3 = __expf(lrelu(asC.w + ad.w) - m.w);
        den.x += w0; den.y += w1; den.z += w2; den.w += w3;
        acc0.x = fmaf(w0, v0c.x, acc0.x); acc0.y = fmaf(w0, v0c.y, acc0.y);
        acc0.z = fmaf(w0, v0c.z, acc0.z); acc0.w = fmaf(w0, v0c.w, acc0.w);
        acc1.x = fmaf(w1, v1c.x, acc1.x); acc1.y = fmaf(w1, v1c.y, acc1.y);
        acc1.z = fmaf(w1, v1c.z, acc1.z); acc1.w = fmaf(w1, v1c.w, acc1.w);
        acc2.x = fmaf(w2, v2c.x, acc2.x); acc2.y = fmaf(w2, v2c.y, acc2.y);
        acc2.z = fmaf(w2, v2c.z, acc2.z); acc2.w = fmaf(w2, v2c.w, acc2.w);
        acc3.x = fmaf(w3, v3c.x, acc3.x); acc3.y = fmaf(w3, v3c.y, acc3.y);
        acc3.z = fmaf(w3, v3c.z, acc3.z); acc3.w = fmaf(w3, v3c.w, acc3.w);
        asC = asN; v0c = v0n; v1c = v1n; v2c = v2n; v3c = v3n;
    }
    float invs[4];
    invs[0] = 1.f / (den.x + 1e-16f); invs[1] = 1.f / (den.y + 1e-16f);
    invs[2] = 1.f / (den.z + 1e-16f); invs[3] = 1.f / (den.w + 1e-16f);
    float4 accs[4] = {acc0, acc1, acc2, acc3};
    #pragma unroll
    for (int h = 0; h < 4; h++) {
        int base = n * HIDDIM + h * NHID + lane * 4;
        float4 bv = *(const float4*)(bias + h * NHID + lane * 4);
        float4 sv = *(const float4*)(skip + base);
        float4 o;
        o.x = eluf(accs[h].x * invs[h] + bv.x + sv.x);
        o.y = eluf(accs[h].y * invs[h] + bv.y + sv.y);
        o.z = eluf(accs[h].z * invs[h] + bv.z + sv.z);
        o.w = eluf(accs[h].w * invs[h] + bv.w + sv.w);
        *(float4*)(out + base) = o;
        __half hx = __float2half(o.x), hy = __float2half(o.y);
        __half hz = __float2half(o.z), hw = __float2half(o.w);
        __half2* ph = (__half2*)(oh + base);
        __half2* pl = (__half2*)(ol + base);
        ph[0] = __halves2half2(hx, hy);
        ph[1] = __halves2half2(hz, hw);
        pl[0] = __halves2half2(__float2half(o.x - __half2float(hx)),
                               __float2half(o.y - __half2float(hy)));
        pl[1] = __halves2half2(__float2half(o.z - __half2float(hz)),
                               __float2half(o.w - __half2float(hw)));
    }
}

// ---------------- final layer: warp per node, 6 heads, lane-parallel max, pipelined ----------------
__global__ void gat_agg_mean6(const float* __restrict__ xw,
                              const float* __restrict__ asrc, const float* __restrict__ adst,
                              float* __restrict__ out, int N) {
    int n = (blockIdx.x * blockDim.x + threadIdx.x) >> 5;
    if (n >= N) return;
    int lane = threadIdx.x & 31;
    bool act = lane < 30;
    int h = act ? (lane / 5) : 5;
    int p = act ? (lane - h * 5) : 0;
    int s0 = g_rowptr[n], s1 = g_rowptr[n + 1];

    float mloc = -1e30f;
    int h2 = act ? (lane % 6) : 0;
    float ad2 = adst[n * NHEADL + h2];
    if (act) {
        for (int i = s0 + lane / 6; i < s1; i += 5) {
            int s = g_csrsrc[i];
            mloc = fmaxf(mloc, lrelu(asrc[s * NHEADL + h2] + ad2));
        }
    }
    #pragma unroll
    for (int off = 6; off <= 24; off <<= 1) {
        int src = lane + off; if (src >= 30) src -= 30;
        float t = __shfl_sync(0xFFFFFFFFu, mloc, src);
        mloc = fmaxf(mloc, t);
    }
    float m  = __shfl_sync(0xFFFFFFFFu, mloc, h);
    float ad = adst[n * NHEADL + h];

    float4 acc0 = {0,0,0,0}, acc1 = {0,0,0,0};
    float den = 0.f;

    float aC = 0.f; float4 v0c = {0,0,0,0}, v1c = {0,0,0,0};
    if (s0 < s1) {
        int s = g_csrsrc[s0];
        aC = asrc[s * NHEADL + h];
        if (act) {
            const float4* row = (const float4*)(xw + (size_t)s * (NHEADL * NCLASS)) + h * 10;
            v0c = row[p]; v1c = row[p + 5];
        }
    }
    for (int i = s0; i < s1; i++) {
        float aN = 0.f; float4 v0n = {0,0,0,0}, v1n = {0,0,0,0};
        if (i + 1 < s1) {
            int s = g_csrsrc[i + 1];
            aN = asrc[s * NHEADL + h];
            if (act) {
                const float4* row = (const float4*)(xw + (size_t)s * (NHEADL * NCLASS)) + h * 10;
                v0n = row[p]; v1n = row[p + 5];
            }
        }
        float w = __expf(lrelu(aC + ad) - m);
        den += w;
        acc0.x = fmaf(w, v0c.x, acc0.x); acc0.y = fmaf(w, v0c.y, acc0.y);
        acc0.z = fmaf(w, v0c.z, acc0.z); acc0.w = fmaf(w, v0c.w, acc0.w);
        acc1.x = fmaf(w, v1c.x, acc1.x); acc1.y = fmaf(w, v1c.y, acc1.y);
        acc1.z = fmaf(w, v1c.z, acc1.z); acc1.w = fmaf(w, v1c.w, acc1.w);
        aC = aN; v0c = v0n; v1c = v1n;
    }
    float sc = act ? (1.f / (den + 1e-16f)) * (1.f / (float)NHEADL) : 0.f;
    acc0.x *= sc; acc0.y *= sc; acc0.z *= sc; acc0.w *= sc;
    acc1.x *= sc; acc1.y *= sc; acc1.z *= sc; acc1.w *= sc;

    #define SHF4(d, v, src) \
        d.x = __shfl_sync(0xFFFFFFFFu, v.x, src); \
        d.y = __shfl_sync(0xFFFFFFFFu, v.y, src); \
        d.z = __shfl_sync(0xFFFFFFFFu, v.z, src); \
        d.w = __shfl_sync(0xFFFFFFFFu, v.w, src);
    float4 t;
    SHF4(t, acc0, (lane + 15) & 31);
    acc0.x += t.x; acc0.y += t.y; acc0.z += t.z; acc0.w += t.w;
    SHF4(t, acc1, (lane + 15) & 31);
    acc1.x += t.x; acc1.y += t.y; acc1.z += t.z; acc1.w += t.w;
    float4 a5, a10, b5, b10;
    SHF4(a5,  acc0, (lane + 5) & 31);
    SHF4(a10, acc0, (lane + 10) & 31);
    SHF4(b5,  acc1, (lane + 5) & 31);
    SHF4(b10, acc1, (lane + 10) & 31);
    if (lane < 5) {
        float4* o = (float4*)(out + (size_t)n * NCLASS);
        float4 c0 = o[lane];
        float4 c1 = o[lane + 5];
        c0.x += acc0.x + a5.x + a10.x; c0.y += acc0.y + a5.y + a10.y;
        c0.z += acc0.z + a5.z + a10.z; c0.w += acc0.w + a5.w + a10.w;
        c1.x += acc1.x + b5.x + b10.x; c1.y += acc1.y + b5.y + b10.y;
        c1.z += acc1.z + b5.z + b10.z; c1.w += acc1.w + b5.w + b10.w;
        o[lane] = c0;
        o[lane + 5] = c1;
    }
    #undef SHF4
}

// ---------------- launch ----------------
extern "C" void kernel_launch(void* const* d_in, const int* in_sizes, int n_in,
                              void* d_out, int out_size) {
    const float* x        = (const float*)d_in[0];
    const void*  ei       = d_in[1];
    const float* W0       = (const float*)d_in[2];
    const float* a_src0   = (const float*)d_in[3];
    const float* a_dst0   = (const float*)d_in[4];
    const float* b0       = (const float*)d_in[5];
    const float* Wskip_in = (const float*)d_in[6];
    const float* W1       = (const float*)d_in[7];
    const float* a_src1   = (const float*)d_in[8];
    const float* a_dst1   = (const float*)d_in[9];
    const float* b1       = (const float*)d_in[10];
    const float* W2       = (const float*)d_in[11];
    const float* a_src2   = (const float*)d_in[12];
    const float* a_dst2   = (const float*)d_in[13];
    const float* b2       = (const float*)d_in[14];
    const float* Wskip_out= (const float*)d_in[15];
    float* out = (float*)d_out;

    int N = in_sizes[0] / NFEAT;
    int E = in_sizes[1] / 2;

    float *XW, *X1, *X2, *SKIP, *ASRC, *ADST;
    __half *AH, *AL, *BT;
    int *deg;
    cudaGetSymbolAddress((void**)&XW,   g_XW);
    cudaGetSymbolAddress((void**)&X1,   g_X1);
    cudaGetSymbolAddress((void**)&X2,   g_X2);
    cudaGetSymbolAddress((void**)&SKIP, g_SKIP);
    cudaGetSymbolAddress((void**)&ASRC, g_ASRC);
    cudaGetSymbolAddress((void**)&ADST, g_ADST);
    cudaGetSymbolAddress((void**)&AH,   g_AH);
    cudaGetSymbolAddress((void**)&AL,   g_AL);
    cudaGetSymbolAddress((void**)&BT,   g_BT);
    cudaGetSymbolAddress((void**)&deg,  g_deg);

    cudaFuncSetAttribute(gemm_split_f16, cudaFuncAttributeMaxDynamicSharedMemorySize, SMEM_GEMM);

    cudaMemsetAsync(deg, 0, 2 * MAXN * sizeof(int));
    detect_i64_kernel<<<1, 32>>>((const int*)ei);

    dim3 blk(256);
    auto cdiv = [](int a, int b) { return (a + b - 1) / b; };
    auto ggrid = [&](int Ncol) { return dim3(cdiv(Ncol, GBN), cdiv(N, GBM)); };

    int gridN = cdiv(N * 32, 256);
    int Nx = N * NFEAT;
    int splitBlk = cdiv(Nx, 256);

    // ---- fused preprocessing (watt + transposes + split + degree) ----
    prep_kernel<<<2208 + splitBlk + cdiv(E, 256), blk>>>(
        x, Nx, splitBlk, ei, E, W0, Wskip_in, W1, W2, Wskip_out,
        a_src0, a_dst0, a_src1, a_dst1, a_src2, a_dst2,
        AH, AL, BT);

    // ---- fork: CSR build (scan+scatter) on side stream, concurrent with GEMM0 ----
    cudaStream_t s2;
    cudaStreamCreateWithFlags(&s2, cudaStreamNonBlocking);
    cudaEvent_t evPrep, evCSR;
    cudaEventCreateWithFlags(&evPrep, cudaEventDisableTiming);
    cudaEventCreateWithFlags(&evCSR,  cudaEventDisableTiming);

    cudaEventRecord(evPrep, 0);
    cudaStreamWaitEvent(s2, evPrep, 0);
    scan_kernel<<<1, 1024, 0, s2>>>(N);
    scatter_kernel<<<cdiv(E, 256), blk, 0, s2>>>(ei, E);
    cudaEventRecord(evCSR, s2);

    // ---- layer 0 GEMM (main stream, overlaps CSR) ----
    gemm_split_f16<<<ggrid(1032), blk, SMEM_GEMM>>>(
        AH, AL, BT + OFF0, nullptr, XW, SKIP, ASRC, ADST,
        HIDDIM, 2 * HIDDIM, NHEAD, N, NFEAT, 1032);

    cudaStreamWaitEvent(0, evCSR, 0);   // agg needs CSR
    gat_agg_concat4<<<gridN, blk>>>(XW, ASRC, ADST, b0, SKIP, X1, AH, AL, N);

    // ---- layer 1 ----
    gemm_split_f16<<<ggrid(520), blk, SMEM_GEMM>>>(
        AH, AL, BT + OFF1, nullptr, XW, XW, ASRC, ADST,
        HIDDIM, HIDDIM, NHEAD, N, HIDDIM, 520);
    gat_agg_concat4<<<gridN, blk>>>(XW, ASRC, ADST, b1, X1, X2, AH, AL, N);

    // ---- layer 2 ----
    gemm_split_f16<<<ggrid(292), blk, SMEM_GEMM>>>(
        AH, AL, BT + OFF2, b2, XW, out, ASRC, ADST,
        NHEADL * NCLASS, NHEADL * NCLASS + NCLASS, NHEADL, N, HIDDIM, 292);
    gat_agg_mean6<<<gridN, blk>>>(XW, ASRC, ADST, out, N);

    cudaEventDestroy(evPrep);
    cudaEventDestroy(evCSR);
    cudaStreamDestroy(s2);
}

// round 14
// speedup vs baseline: 1.1290x; 1.0318x over previous
#include <cuda_runtime.h>
#include <cuda_fp16.h>
#include <math.h>
#include <stdint.h>

// ---------------- problem constants ----------------
#define NFEAT   256
#define NHID    128
#define NHEAD   4
#define NHEADL  6
#define NCLASS  40
#define HIDDIM  (NHID*NHEAD)      // 512
#define MAXN    10000
#define MAXE    160000
#define MAXEDGE (MAXE + MAXN)
#define NEG_SLOPE 0.2f

// BT arena row offsets (halves)
#define OFF0 0
#define OFF1 264192
#define OFF2 530432
#define BT_TOTAL 679936

// ---------------- scratch (static device memory) ----------------
__device__ float g_XW [MAXN * HIDDIM];
__device__ float g_X1 [MAXN * HIDDIM];
__device__ float g_X2 [MAXN * HIDDIM];
__device__ float g_SKIP[MAXN * HIDDIM];
__device__ float g_ASRC[MAXN * NHEADL];
__device__ float g_ADST[MAXN * NHEADL];
__device__ __half g_AH[MAXN * HIDDIM];
__device__ __half g_AL[MAXN * HIDDIM];
__device__ __half g_XWH[MAXN * HIDDIM];      // fp16 message payload
__device__ __half g_BT[BT_TOTAL];
__device__ int   g_rowptr[MAXN + 1];
__device__ int   g_deg [2 * MAXN];
__device__ int   g_csrsrc[MAXEDGE];
__device__ int   g_is64;

// ---------------- edge dtype detection ----------------
__global__ void detect_i64_kernel(const int* w) {
    if (threadIdx.x == 0) {
        int all0 = 1;
        #pragma unroll
        for (int i = 0; i < 64; i++) if (w[2*i + 1] != 0) all0 = 0;
        g_is64 = all0;
    }
}

__device__ __forceinline__ int edge_at(const void* ei, long long idx) {
    if (g_is64) return (int)((const long long*)ei)[idx];
    return ((const int*)ei)[idx];
}

// scan + self-loop placement fused; batched predicated loads
__global__ void scan_kernel(int n) {
    const int CH = (n + 1023) >> 10;
    int t = threadIdx.x;
    int base = t * CH;
    int vals[16];
    #pragma unroll
    for (int j = 0; j < 16; j++) {
        int idx = base + j;
        vals[j] = (j < CH && idx < n) ? (g_deg[idx] + 1) : 0;
    }
    int local[16];
    int run = 0;
    #pragma unroll
    for (int j = 0; j < 16; j++) { run += vals[j]; local[j] = run; }
    int lane = t & 31, wid = t >> 5;
    int x = run;
    #pragma unroll
    for (int o = 1; o < 32; o <<= 1) {
        int y = __shfl_up_sync(0xFFFFFFFFu, x, o);
        if (lane >= o) x += y;
    }
    __shared__ int wsum[32];
    if (lane == 31) wsum[wid] = x;
    __syncthreads();
    if (wid == 0) {
        int w = wsum[lane];
        #pragma unroll
        for (int o = 1; o < 32; o <<= 1) {
            int y = __shfl_up_sync(0xFFFFFFFFu, w, o);
            if (lane >= o) w += y;
        }
        wsum[lane] = w;
    }
    __syncthreads();
    int excl = x - run + (wid > 0 ? wsum[wid - 1] : 0);
    if (t == 0) g_rowptr[0] = 0;
    #pragma unroll
    for (int j = 0; j < 16; j++) {
        int idx = base + j;
        if (j < CH && idx < n) {
            int rp = excl + local[j];
            g_rowptr[idx + 1] = rp;
            g_csrsrc[rp - 1] = idx;
        }
    }
}

__global__ void scatter_kernel(const void* ei, int E) {
    int e = blockIdx.x * blockDim.x + threadIdx.x;
    if (e < E) {
        int d = edge_at(ei, (long long)E + e);
        int s = edge_at(ei, e);
        int p = g_rowptr[d] + atomicAdd(&g_deg[MAXN + d], 1);
        g_csrsrc[p] = s;
    }
}

// ---------------- fused preprocessing: watt + transpose + A-split + degree ----------------
__global__ void prep_kernel(const float* __restrict__ x, int Nx, int splitBlk,
                            const void* __restrict__ ei, int E,
                            const float* __restrict__ W0, const float* __restrict__ Wsi,
                            const float* __restrict__ W1, const float* __restrict__ W2,
                            const float* __restrict__ Wso,
                            const float* __restrict__ as0, const float* __restrict__ ad0,
                            const float* __restrict__ as1, const float* __restrict__ ad1,
                            const float* __restrict__ as2, const float* __restrict__ ad2,
                            __half* __restrict__ AH, __half* __restrict__ AL,
                            __half* __restrict__ BT) {
    __shared__ float t[32][33];
    int b = blockIdx.x;
    int tid = threadIdx.x;
    if (b < 1536) {
        int gw = b * 8 + (tid >> 5);
        int lane = tid & 31;
        const float *W, *att; int K, C, k, j, attRow, Ww; __half* dst;
        if (gw < 2048)       { int q = gw;        k = q >> 3; j = q & 7;  W = W0; att = (j & 1) ? ad0 : as0; K = 256; C = 128; Ww = 512; attRow = 1024; dst = BT + OFF0; }
        else if (gw < 6144)  { int q = gw - 2048; k = q >> 3; j = q & 7;  W = W1; att = (j & 1) ? ad1 : as1; K = 512; C = 128; Ww = 512; attRow = 512;  dst = BT + OFF1; }
        else                 { int q = gw - 6144; k = q / 12; j = q % 12; W = W2; att = (j & 1) ? ad2 : as2; K = 512; C = 40;  Ww = 240; attRow = 280;  dst = BT + OFF2; }
        int h = j >> 1;
        float s = 0.f;
        for (int c = lane; c < C; c += 32)
            s = fmaf(W[(size_t)k * Ww + h * C + c], att[h * C + c], s);
        #pragma unroll
        for (int o = 16; o; o >>= 1) s += __shfl_xor_sync(0xFFFFFFFFu, s, o);
        if (lane == 0) dst[(size_t)(attRow + j) * K + k] = __float2half(s);
    } else if (b < 2208) {
        int bb = b - 1536;
        const float* src; int K, Ncol, rowOff, tile, ntx; __half* dst;
        if (bb < 128)      { src = W0;  K = 256; Ncol = 512; rowOff = 0;   dst = BT + OFF0; tile = bb;       ntx = 16; }
        else if (bb < 256) { src = Wsi; K = 256; Ncol = 512; rowOff = 512; dst = BT + OFF0; tile = bb - 128; ntx = 16; }
        else if (bb < 512) { src = W1;  K = 512; Ncol = 512; rowOff = 0;   dst = BT + OFF1; tile = bb - 256; ntx = 16; }
        else if (bb < 640) { src = W2;  K = 512; Ncol = 240; rowOff = 0;   dst = BT + OFF2; tile = bb - 512; ntx = 8;  }
        else               { src = Wso; K = 512; Ncol = 40;  rowOff = 240; dst = BT + OFF2; tile = bb - 640; ntx = 2;  }
        int kb = (tile / ntx) * 32, nb = (tile % ntx) * 32;
        int tx = tid & 31, ty = tid >> 5;
        #pragma unroll
        for (int j = ty; j < 32; j += 8) {
            int k = kb + j, n = nb + tx;
            t[j][tx] = (k < K && n < Ncol) ? src[(size_t)k * Ncol + n] : 0.f;
        }
        __syncthreads();
        #pragma unroll
        for (int j = ty; j < 32; j += 8) {
            int n = nb + j, k = kb + tx;
            if (n < Ncol && k < K)
                dst[(size_t)(n + rowOff) * K + k] = __float2half(t[tx][j]);
        }
    } else if (b < 2208 + splitBlk) {
        int i = (b - 2208) * 256 + tid;
        if (i < Nx) {
            float v = x[i];
            __half h = __float2half(v);
            AH[i] = h;
            AL[i] = __float2half(v - __half2float(h));
        }
    } else {
        int e = (b - 2208 - splitBlk) * 256 + tid;
        if (e < E) atomicAdd(&g_deg[edge_at(ei, (long long)E + e)], 1);
    }
}

// ---------------- split-fp16 tensor-core GEMM, 3-stage pipeline ----------------
#define GBM 128
#define GBN 64
#define GBK 32
#define APADB 80
#define ABYTES (GBM*APADB)
#define BBYTES (GBN*APADB)
#define STAGEB (2*ABYTES + BBYTES)
#define NSTAGE 3
#define SMEM_GEMM (NSTAGE*STAGEB)

__device__ __forceinline__ void cp16(uint32_t dst, const void* src) {
    asm volatile("cp.async.cg.shared.global [%0], [%1], 16;\n" :: "r"(dst), "l"(src));
}

__device__ __forceinline__ void ldsm4(uint32_t* r, uint32_t addr) {
    asm volatile("ldmatrix.sync.aligned.m8n8.x4.shared.b16 {%0,%1,%2,%3}, [%4];"
                 : "=r"(r[0]), "=r"(r[1]), "=r"(r[2]), "=r"(r[3]) : "r"(addr));
}

__device__ __forceinline__ void mma16816(float* c, const uint32_t* a, const uint32_t* b) {
    asm volatile("mma.sync.aligned.m16n8k16.row.col.f32.f16.f16.f32 "
                 "{%0,%1,%2,%3}, {%4,%5,%6,%7}, {%8,%9}, {%0,%1,%2,%3};"
                 : "+f"(c[0]), "+f"(c[1]), "+f"(c[2]), "+f"(c[3])
                 : "r"(a[0]), "r"(a[1]), "r"(a[2]), "r"(a[3]), "r"(b[0]), "r"(b[1]));
}

__global__ void __launch_bounds__(256, 2)
gemm_split_f16(const __half* __restrict__ AH, const __half* __restrict__ AL,
               const __half* __restrict__ BT,
               const float* __restrict__ bias2,
               float* __restrict__ C, __half* __restrict__ Ch,
               float* __restrict__ C2,
               float* __restrict__ ASRC, float* __restrict__ ADST,
               int split1, int split2, int Hatt,
               int M, int K, int Ntot) {
    extern __shared__ char smem[];
    uint32_t sbase = (uint32_t)__cvta_generic_to_shared(smem);
    int tid = threadIdx.x, lane = tid & 31, warp = tid >> 5;
    int bm = blockIdx.y * GBM, bn = blockIdx.x * GBN;
    int m0 = (warp >> 1) * 32, n0 = (warp & 1) * 32;
    int nIter = K / GBK;

    float acc[2][4][4] = {};

    auto stage_load = [&](int it, int s) {
        int k0 = it * GBK;
        uint32_t sb = sbase + s * STAGEB;
        #pragma unroll
        for (int rep = 0; rep < 2; rep++) {
            int idx = tid + rep * 256;
            int r = idx >> 2, ch = idx & 3;
            int ra = bm + r; if (ra >= M) ra = M - 1;
            size_t off = (size_t)ra * K + k0 + ch * 8;
            cp16(sb + r * APADB + ch * 16, AH + off);
            cp16(sb + ABYTES + r * APADB + ch * 16, AL + off);
        }
        {
            int r = tid >> 2, ch = tid & 3;
            int ra = bn + r; if (ra >= Ntot) ra = Ntot - 1;
            size_t off = (size_t)ra * K + k0 + ch * 8;
            cp16(sb + 2 * ABYTES + r * APADB + ch * 16, BT + off);
        }
    };

    int aRow = lane & 15;
    int aKby = (lane >> 4) * 16;
    int bRow = (lane & 7) + ((lane >> 4) << 3);
    int bKby = ((lane >> 3) & 1) * 16;

    stage_load(0, 0);
    asm volatile("cp.async.commit_group;\n");
    if (nIter > 1) stage_load(1, 1);
    asm volatile("cp.async.commit_group;\n");

    for (int it = 0; it < nIter; it++) {
        int s = it % NSTAGE;
        asm volatile("cp.async.wait_group 1;\n");
        __syncthreads();
        if (it + 2 < nIter) stage_load(it + 2, (it + 2) % NSTAGE);
        asm volatile("cp.async.commit_group;\n");

        uint32_t sb  = sbase + s * STAGEB;
        uint32_t pAH = sb + (m0 + aRow) * APADB + aKby;
        uint32_t pAL = pAH + ABYTES;
        uint32_t pB  = sb + 2 * ABYTES + (n0 + bRow) * APADB + bKby;

        #pragma unroll
        for (int ks = 0; ks < 2; ks++) {
            int kb = ks * 32;
            uint32_t ah[2][4], al[2][4];
            ldsm4(ah[0], pAH + kb);
            ldsm4(ah[1], pAH + 16 * APADB + kb);
            ldsm4(al[0], pAL + kb);
            ldsm4(al[1], pAL + 16 * APADB + kb);
            uint32_t b01[4], b23[4];
            ldsm4(b01, pB + kb);
            ldsm4(b23, pB + 16 * APADB + kb);
            const uint32_t* bf[4] = {b01, b01 + 2, b23, b23 + 2};
            #pragma unroll
            for (int mt = 0; mt < 2; mt++)
                #pragma unroll
                for (int nt = 0; nt < 4; nt++) mma16816(acc[mt][nt], ah[mt], bf[nt]);
            #pragma unroll
            for (int mt = 0; mt < 2; mt++)
                #pragma unroll
                for (int nt = 0; nt < 4; nt++) mma16816(acc[mt][nt], al[mt], bf[nt]);
        }
        __syncthreads();
    }

    int attEnd = split2 + 2 * Hatt;
    #pragma unroll
    for (int mt = 0; mt < 2; mt++) {
        #pragma unroll
        for (int nt = 0; nt < 4; nt++) {
            int r = bm + m0 + mt * 16 + (lane >> 2);
            int c = bn + n0 + nt * 8 + (lane & 3) * 2;   // even
            #pragma unroll
            for (int half = 0; half < 2; half++) {
                int rr = r + half * 8;
                if (rr >= M) continue;
                float v0 = acc[mt][nt][half * 2 + 0];
                float v1 = acc[mt][nt][half * 2 + 1];
                if (c < split1) {        // pair fully inside (split1 even)
                    C[(size_t)rr * split1 + c]     = v0;
                    C[(size_t)rr * split1 + c + 1] = v1;
                    *(__half2*)(Ch + (size_t)rr * split1 + c) =
                        __halves2half2(__float2half(v0), __float2half(v1));
                } else {
                    #pragma unroll
                    for (int j = 0; j < 2; j++) {
                        int cc = c + j;
                        float v = j ? v1 : v0;
                        if (cc < split2) {
                            int c2 = cc - split1;
                            if (bias2) v += bias2[c2];
                            C2[(size_t)rr * (split2 - split1) + c2] = v;
                        } else if (cc < attEnd) {
                            int ca = cc - split2;
                            int h = ca >> 1;
                            ((ca & 1) ? ADST : ASRC)[(size_t)rr * Hatt + h] = v;
                        }
                    }
                }
            }
        }
    }
}

__device__ __forceinline__ float lrelu(float x) { return x > 0.f ? x : NEG_SLOPE * x; }
__device__ __forceinline__ float eluf(float x)  { return x > 0.f ? x : expm1f(x); }

#define H2FMA(u, w, a0, a1) { \
    float2 _f = __half22float2(*(const __half2*)&(u)); \
    (a0) = fmaf((w), _f.x, (a0)); (a1) = fmaf((w), _f.y, (a1)); }

// ---------------- GAT aggregation: warp per node, fp16 payload, coalesced lane map ----------------
// lane owns halves [8l, 8l+8) (head lane>>4) and [256+8l, 256+8l+8) (head 2+(lane>>4))
__global__ void gat_agg_concat4(const __half* __restrict__ xwh,
                                const float* __restrict__ asrc, const float* __restrict__ adst,
                                const float* __restrict__ bias, const float* __restrict__ skip,
                                float* __restrict__ out,
                                __half* __restrict__ oh, __half* __restrict__ ol,
                                int N) {
    int n = (blockIdx.x * blockDim.x + threadIdx.x) >> 5;
    if (n >= N) return;
    int lane = threadIdx.x & 31;
    int hsel = lane >> 4;     // 0 or 1
    int s0 = g_rowptr[n], s1 = g_rowptr[n + 1];
    float4 ad = *(const float4*)(adst + n * 4);

    float4 m = make_float4(-1e30f, -1e30f, -1e30f, -1e30f);
    for (int i = s0 + lane; i < s1; i += 32) {
        int s = g_csrsrc[i];
        float4 as = *(const float4*)(asrc + s * 4);
        m.x = fmaxf(m.x, lrelu(as.x + ad.x));
        m.y = fmaxf(m.y, lrelu(as.y + ad.y));
        m.z = fmaxf(m.z, lrelu(as.z + ad.z));
        m.w = fmaxf(m.w, lrelu(as.w + ad.w));
    }
    #pragma unroll
    for (int o = 16; o; o >>= 1) {
        m.x = fmaxf(m.x, __shfl_xor_sync(0xFFFFFFFFu, m.x, o));
        m.y = fmaxf(m.y, __shfl_xor_sync(0xFFFFFFFFu, m.y, o));
        m.z = fmaxf(m.z, __shfl_xor_sync(0xFFFFFFFFu, m.z, o));
        m.w = fmaxf(m.w, __shfl_xor_sync(0xFFFFFFFFu, m.w, o));
    }

    float accA[8] = {}, accB[8] = {};
    float4 den = {0,0,0,0};

    float4 asC = {0,0,0,0}; uint4 Ac = {0,0,0,0}, Bc = {0,0,0,0};
    if (s0 < s1) {
        int s = g_csrsrc[s0];
        asC = *(const float4*)(asrc + s * 4);
        const uint4* row = (const uint4*)(xwh + (size_t)s * HIDDIM);
        Ac = row[lane]; Bc = row[32 + lane];
    }
    for (int i = s0; i < s1; i++) {
        float4 asN = {0,0,0,0}; uint4 An = {0,0,0,0}, Bn = {0,0,0,0};
        if (i + 1 < s1) {
            int s = g_csrsrc[i + 1];
            asN = *(const float4*)(asrc + s * 4);
            const uint4* row = (const uint4*)(xwh + (size_t)s * HIDDIM);
            An = row[lane]; Bn = row[32 + lane];
        }
        float w0 = __expf(lrelu(asC.x + ad.x) - m.x);
        float w1 = __expf(lrelu(asC.y + ad.y) - m.y);
        float w2 = __expf(lrelu(asC.z + ad.z) - m.z);
        float w3 = __expf(lrelu(asC.w + ad.w) - m.w);
        den.x += w0; den.y += w1; den.z += w2; den.w += w3;
        float wa = hsel ? w1 : w0;
        float wb = hsel ? w3 : w2;
        H2FMA(Ac.x, wa, accA[0], accA[1]);
        H2FMA(Ac.y, wa, accA[2], accA[3]);
        H2FMA(Ac.z, wa, accA[4], accA[5]);
        H2FMA(Ac.w, wa, accA[6], accA[7]);
        H2FMA(Bc.x, wb, accB[0], accB[1]);
        H2FMA(Bc.y, wb, accB[2], accB[3]);
        H2FMA(Bc.z, wb, accB[4], accB[5]);
        H2FMA(Bc.w, wb, accB[6], accB[7]);
        asC = asN; Ac = An; Bc = Bn;
    }
    float invs[4];
    invs[0] = 1.f / (den.x + 1e-16f); invs[1] = 1.f / (den.y + 1e-16f);
    invs[2] = 1.f / (den.z + 1e-16f); invs[3] = 1.f / (den.w + 1e-16f);
    float invA = invs[hsel], invB = invs[2 + hsel];

    #pragma unroll
    for (int g = 0; g < 2; g++) {
        const float* acc = g ? accB : accA;
        float inv = g ? invB : invA;
        int ch = g * 256 + lane * 8;
        int base = n * HIDDIM + ch;
        #pragma unroll
        for (int q = 0; q < 2; q++) {
            float4 bv = *(const float4*)(bias + ch + q * 4);
            float4 sv = *(const float4*)(skip + base + q * 4);
            float4 o;
            o.x = eluf(acc[q*4+0] * inv + bv.x + sv.x);
            o.y = eluf(acc[q*4+1] * inv + bv.y + sv.y);
            o.z = eluf(acc[q*4+2] * inv + bv.z + sv.z);
            o.w = eluf(acc[q*4+3] * inv + bv.w + sv.w);
            *(float4*)(out + base + q * 4) = o;
            __half hx = __float2half(o.x), hy = __float2half(o.y);
            __half hz = __float2half(o.z), hw = __float2half(o.w);
            *(__half2*)(oh + base + q * 4)     = __halves2half2(hx, hy);
            *(__half2*)(oh + base + q * 4 + 2) = __halves2half2(hz, hw);
            *(__half2*)(ol + base + q * 4)     = __halves2half2(
                __float2half(o.x - __half2float(hx)), __float2half(o.y - __half2float(hy)));
            *(__half2*)(ol + base + q * 4 + 2) = __halves2half2(
                __float2half(o.z - __half2float(hz)), __float2half(o.w - __half2float(hw)));
        }
    }
}

// ---------------- final layer: warp per node, fp16 payload, one coalesced uint4/edge ----------------
// lane<30: h = lane/5, p = lane%5; lane owns halves [lane*8, lane*8+8) = head h channels 8p..8p+7
__global__ void gat_agg_mean6(const __half* __restrict__ xwh,
                              const float* __restrict__ asrc, const float* __restrict__ adst,
                              float* __restrict__ out, int N) {
    int n = (blockIdx.x * blockDim.x + threadIdx.x) >> 5;
    if (n >= N) return;
    int lane = threadIdx.x & 31;
    bool act = lane < 30;
    int h = act ? (lane / 5) : 5;
    int s0 = g_rowptr[n], s1 = g_rowptr[n + 1];

    float mloc = -1e30f;
    int h2 = act ? (lane % 6) : 0;
    float ad2 = adst[n * NHEADL + h2];
    if (act) {
        for (int i = s0 + lane / 6; i < s1; i += 5) {
            int s = g_csrsrc[i];
            mloc = fmaxf(mloc, lrelu(asrc[s * NHEADL + h2] + ad2));
        }
    }
    #pragma unroll
    for (int off = 6; off <= 24; off <<= 1) {
        int src = lane + off; if (src >= 30) src -= 30;
        float t = __shfl_sync(0xFFFFFFFFu, mloc, src);
        mloc = fmaxf(mloc, t);
    }
    float m  = __shfl_sync(0xFFFFFFFFu, mloc, h);
    float ad = adst[n * NHEADL + h];

    float4 acc0 = {0,0,0,0}, acc1 = {0,0,0,0};
    float den = 0.f;

    float aC = 0.f; uint4 Vc = {0,0,0,0};
    if (s0 < s1) {
        int s = g_csrsrc[s0];
        aC = asrc[s * NHEADL + h];
        if (act) Vc = *(const uint4*)(xwh + (size_t)s * (NHEADL * NCLASS) + lane * 8);
    }
    for (int i = s0; i < s1; i++) {
        float aN = 0.f; uint4 Vn = {0,0,0,0};
        if (i + 1 < s1) {
            int s = g_csrsrc[i + 1];
            aN = asrc[s * NHEADL + h];
            if (act) Vn = *(const uint4*)(xwh + (size_t)s * (NHEADL * NCLASS) + lane * 8);
        }
        float w = __expf(lrelu(aC + ad) - m);
        den += w;
        H2FMA(Vc.x, w, acc0.x, acc0.y);
        H2FMA(Vc.y, w, acc0.z, acc0.w);
        H2FMA(Vc.z, w, acc1.x, acc1.y);
        H2FMA(Vc.w, w, acc1.z, acc1.w);
        aC = aN; Vc = Vn;
    }
    float sc = act ? (1.f / (den + 1e-16f)) * (1.f / (float)NHEADL) : 0.f;
    acc0.x *= sc; acc0.y *= sc; acc0.z *= sc; acc0.w *= sc;
    acc1.x *= sc; acc1.y *= sc; acc1.z *= sc; acc1.w *= sc;

    #define SHF4(d, v, src) \
        d.x = __shfl_sync(0xFFFFFFFFu, v.x, src); \
        d.y = __shfl_sync(0xFFFFFFFFu, v.y, src); \
        d.z = __shfl_sync(0xFFFFFFFFu, v.z, src); \
        d.w = __shfl_sync(0xFFFFFFFFu, v.w, src);
    float4 t;
    SHF4(t, acc0, (lane + 15) & 31);
    acc0.x += t.x; acc0.y += t.y; acc0.z += t.z; acc0.w += t.w;
    SHF4(t, acc1, (lane + 15) & 31);
    acc1.x += t.x; acc1.y += t.y; acc1.z += t.z; acc1.w += t.w;
    float4 a5, a10, b5, b10;
    SHF4(a5,  acc0, (lane + 5) & 31);
    SHF4(a10, acc0, (lane + 10) & 31);
    SHF4(b5,  acc1, (lane + 5) & 31);
    SHF4(b10, acc1, (lane + 10) & 31);
    if (lane < 5) {
        float4* o = (float4*)(out + (size_t)n * NCLASS + lane * 8);
        float4 c0 = o[0];
        float4 c1 = o[1];
        c0.x += acc0.x + a5.x + a10.x; c0.y += acc0.y + a5.y + a10.y;
        c0.z += acc0.z + a5.z + a10.z; c0.w += acc0.w + a5.w + a10.w;
        c1.x += acc1.x + b5.x + b10.x; c1.y += acc1.y + b5.y + b10.y;
        c1.z += acc1.z + b5.z + b10.z; c1.w += acc1.w + b5.w + b10.w;
        o[0] = c0;
        o[1] = c1;
    }
    #undef SHF4
}

// ---------------- launch ----------------
extern "C" void kernel_launch(void* const* d_in, const int* in_sizes, int n_in,
                              void* d_out, int out_size) {
    const float* x        = (const float*)d_in[0];
    const void*  ei       = d_in[1];
    const float* W0       = (const float*)d_in[2];
    const float* a_src0   = (const float*)d_in[3];
    const float* a_dst0   = (const float*)d_in[4];
    const float* b0       = (const float*)d_in[5];
    const float* Wskip_in = (const float*)d_in[6];
    const float* W1       = (const float*)d_in[7];
    const float* a_src1   = (const float*)d_in[8];
    const float* a_dst1   = (const float*)d_in[9];
    const float* b1       = (const float*)d_in[10];
    const float* W2       = (const float*)d_in[11];
    const float* a_src2   = (const float*)d_in[12];
    const float* a_dst2   = (const float*)d_in[13];
    const float* b2       = (const float*)d_in[14];
    const float* Wskip_out= (const float*)d_in[15];
    float* out = (float*)d_out;

    int N = in_sizes[0] / NFEAT;
    int E = in_sizes[1] / 2;

    float *XW, *X1, *X2, *SKIP, *ASRC, *ADST;
    __half *AH, *AL, *XWH, *BT;
    int *deg;
    cudaGetSymbolAddress((void**)&XW,   g_XW);
    cudaGetSymbolAddress((void**)&X1,   g_X1);
    cudaGetSymbolAddress((void**)&X2,   g_X2);
    cudaGetSymbolAddress((void**)&SKIP, g_SKIP);
    cudaGetSymbolAddress((void**)&ASRC, g_ASRC);
    cudaGetSymbolAddress((void**)&ADST, g_ADST);
    cudaGetSymbolAddress((void**)&AH,   g_AH);
    cudaGetSymbolAddress((void**)&AL,   g_AL);
    cudaGetSymbolAddress((void**)&XWH,  g_XWH);
    cudaGetSymbolAddress((void**)&BT,   g_BT);
    cudaGetSymbolAddress((void**)&deg,  g_deg);

    cudaFuncSetAttribute(gemm_split_f16, cudaFuncAttributeMaxDynamicSharedMemorySize, SMEM_GEMM);

    cudaMemsetAsync(deg, 0, 2 * MAXN * sizeof(int));
    detect_i64_kernel<<<1, 32>>>((const int*)ei);

    dim3 blk(256);
    auto cdiv = [](int a, int b) { return (a + b - 1) / b; };
    auto ggrid = [&](int Ncol) { return dim3(cdiv(Ncol, GBN), cdiv(N, GBM)); };

    int gridN = cdiv(N * 32, 256);
    int Nx = N * NFEAT;
    int splitBlk = cdiv(Nx, 256);

    // ---- fused preprocessing ----
    prep_kernel<<<2208 + splitBlk + cdiv(E, 256), blk>>>(
        x, Nx, splitBlk, ei, E, W0, Wskip_in, W1, W2, Wskip_out,
        a_src0, a_dst0, a_src1, a_dst1, a_src2, a_dst2,
        AH, AL, BT);

    // ---- fork: CSR build on side stream, overlapped with GEMM0 ----
    cudaStream_t s2;
    cudaStreamCreateWithFlags(&s2, cudaStreamNonBlocking);
    cudaEvent_t evPrep, evCSR;
    cudaEventCreateWithFlags(&evPrep, cudaEventDisableTiming);
    cudaEventCreateWithFlags(&evCSR,  cudaEventDisableTiming);

    cudaEventRecord(evPrep, 0);
    cudaStreamWaitEvent(s2, evPrep, 0);
    scan_kernel<<<1, 1024, 0, s2>>>(N);
    scatter_kernel<<<cdiv(E, 256), blk, 0, s2>>>(ei, E);
    cudaEventRecord(evCSR, s2);

    // ---- layer 0 GEMM ----
    gemm_split_f16<<<ggrid(1032), blk, SMEM_GEMM>>>(
        AH, AL, BT + OFF0, nullptr, XW, XWH, SKIP, ASRC, ADST,
        HIDDIM, 2 * HIDDIM, NHEAD, N, NFEAT, 1032);

    cudaStreamWaitEvent(0, evCSR, 0);
    gat_agg_concat4<<<gridN, blk>>>(XWH, ASRC, ADST, b0, SKIP, X1, AH, AL, N);

    // ---- layer 1 ----
    gemm_split_f16<<<ggrid(520), blk, SMEM_GEMM>>>(
        AH, AL, BT + OFF1, nullptr, XW, XWH, XW, ASRC, ADST,
        HIDDIM, HIDDIM, NHEAD, N, HIDDIM, 520);
    gat_agg_concat4<<<gridN, blk>>>(XWH, ASRC, ADST, b1, X1, X2, AH, AL, N);

    // ---- layer 2 ----
    gemm_split_f16<<<ggrid(292), blk, SMEM_GEMM>>>(
        AH, AL, BT + OFF2, b2, XW, XWH, out, ASRC, ADST,
        NHEADL * NCLASS, NHEADL * NCLASS + NCLASS, NHEADL, N, HIDDIM, 292);
    gat_agg_mean6<<<gridN, blk>>>(XWH, ASRC, ADST, out, N);

    cudaEventDestroy(evPrep);
    cudaEventDestroy(evCSR);
    cudaStreamDestroy(s2);
}

// round 15
// speedup vs baseline: 1.2849x; 1.1381x over previous
#include <cuda_runtime.h>
#include <cuda_fp16.h>
#include <math.h>
#include <stdint.h>

// ---------------- problem constants ----------------
#define NFEAT   256
#define NHID    128
#define NHEAD   4
#define NHEADL  6
#define NCLASS  40
#define HIDDIM  (NHID*NHEAD)      // 512
#define MAXN    10000
#define MAXE    160000
#define MAXEDGE (MAXE + MAXN)
#define NEG_SLOPE 0.2f

// BT arena row offsets (halves)
#define OFF0 0
#define OFF1 264192
#define OFF2 530432
#define BT_TOTAL 679936

// ---------------- scratch (static device memory) ----------------
__device__ float g_XW [MAXN * HIDDIM];
__device__ float g_X1 [MAXN * HIDDIM];
__device__ float g_X2 [MAXN * HIDDIM];
__device__ float g_SKIP[MAXN * HIDDIM];
__device__ float g_ASRC[MAXN * NHEADL];
__device__ float g_ADST[MAXN * NHEADL];
__device__ __half g_AH[MAXN * HIDDIM];       // fp16 A operand
__device__ __half g_XWH[MAXN * HIDDIM];      // fp16 message payload
__device__ __half g_BT[BT_TOTAL];
__device__ int   g_rowptr[MAXN + 1];
__device__ int   g_deg [2 * MAXN];
__device__ int   g_csrsrc[MAXEDGE];
__device__ int   g_is64;

// ---------------- edge dtype detection ----------------
__global__ void detect_i64_kernel(const int* w) {
    if (threadIdx.x == 0) {
        int all0 = 1;
        #pragma unroll
        for (int i = 0; i < 64; i++) if (w[2*i + 1] != 0) all0 = 0;
        g_is64 = all0;
    }
}

__device__ __forceinline__ int edge_at(const void* ei, long long idx) {
    if (g_is64) return (int)((const long long*)ei)[idx];
    return ((const int*)ei)[idx];
}

// scan + self-loop placement fused; batched predicated loads
__global__ void scan_kernel(int n) {
    const int CH = (n + 1023) >> 10;
    int t = threadIdx.x;
    int base = t * CH;
    int vals[16];
    #pragma unroll
    for (int j = 0; j < 16; j++) {
        int idx = base + j;
        vals[j] = (j < CH && idx < n) ? (g_deg[idx] + 1) : 0;
    }
    int local[16];
    int run = 0;
    #pragma unroll
    for (int j = 0; j < 16; j++) { run += vals[j]; local[j] = run; }
    int lane = t & 31, wid = t >> 5;
    int x = run;
    #pragma unroll
    for (int o = 1; o < 32; o <<= 1) {
        int y = __shfl_up_sync(0xFFFFFFFFu, x, o);
        if (lane >= o) x += y;
    }
    __shared__ int wsum[32];
    if (lane == 31) wsum[wid] = x;
    __syncthreads();
    if (wid == 0) {
        int w = wsum[lane];
        #pragma unroll
        for (int o = 1; o < 32; o <<= 1) {
            int y = __shfl_up_sync(0xFFFFFFFFu, w, o);
            if (lane >= o) w += y;
        }
        wsum[lane] = w;
    }
    __syncthreads();
    int excl = x - run + (wid > 0 ? wsum[wid - 1] : 0);
    if (t == 0) g_rowptr[0] = 0;
    #pragma unroll
    for (int j = 0; j < 16; j++) {
        int idx = base + j;
        if (j < CH && idx < n) {
            int rp = excl + local[j];
            g_rowptr[idx + 1] = rp;
            g_csrsrc[rp - 1] = idx;
        }
    }
}

__global__ void scatter_kernel(const void* ei, int E) {
    int e = blockIdx.x * blockDim.x + threadIdx.x;
    if (e < E) {
        int d = edge_at(ei, (long long)E + e);
        int s = edge_at(ei, e);
        int p = g_rowptr[d] + atomicAdd(&g_deg[MAXN + d], 1);
        g_csrsrc[p] = s;
    }
}

// ---------------- fused preprocessing: watt + transpose + A-convert + degree ----------------
__global__ void prep_kernel(const float* __restrict__ x, int Nx, int splitBlk,
                            const void* __restrict__ ei, int E,
                            const float* __restrict__ W0, const float* __restrict__ Wsi,
                            const float* __restrict__ W1, const float* __restrict__ W2,
                            const float* __restrict__ Wso,
                            const float* __restrict__ as0, const float* __restrict__ ad0,
                            const float* __restrict__ as1, const float* __restrict__ ad1,
                            const float* __restrict__ as2, const float* __restrict__ ad2,
                            __half* __restrict__ AH, __half* __restrict__ BT) {
    __shared__ float t[32][33];
    int b = blockIdx.x;
    int tid = threadIdx.x;
    if (b < 1536) {
        int gw = b * 8 + (tid >> 5);
        int lane = tid & 31;
        const float *W, *att; int K, C, k, j, attRow, Ww; __half* dst;
        if (gw < 2048)       { int q = gw;        k = q >> 3; j = q & 7;  W = W0; att = (j & 1) ? ad0 : as0; K = 256; C = 128; Ww = 512; attRow = 1024; dst = BT + OFF0; }
        else if (gw < 6144)  { int q = gw - 2048; k = q >> 3; j = q & 7;  W = W1; att = (j & 1) ? ad1 : as1; K = 512; C = 128; Ww = 512; attRow = 512;  dst = BT + OFF1; }
        else                 { int q = gw - 6144; k = q / 12; j = q % 12; W = W2; att = (j & 1) ? ad2 : as2; K = 512; C = 40;  Ww = 240; attRow = 280;  dst = BT + OFF2; }
        int h = j >> 1;
        float s = 0.f;
        for (int c = lane; c < C; c += 32)
            s = fmaf(W[(size_t)k * Ww + h * C + c], att[h * C + c], s);
        #pragma unroll
        for (int o = 16; o; o >>= 1) s += __shfl_xor_sync(0xFFFFFFFFu, s, o);
        if (lane == 0) dst[(size_t)(attRow + j) * K + k] = __float2half(s);
    } else if (b < 2208) {
        int bb = b - 1536;
        const float* src; int K, Ncol, rowOff, tile, ntx; __half* dst;
        if (bb < 128)      { src = W0;  K = 256; Ncol = 512; rowOff = 0;   dst = BT + OFF0; tile = bb;       ntx = 16; }
        else if (bb < 256) { src = Wsi; K = 256; Ncol = 512; rowOff = 512; dst = BT + OFF0; tile = bb - 128; ntx = 16; }
        else if (bb < 512) { src = W1;  K = 512; Ncol = 512; rowOff = 0;   dst = BT + OFF1; tile = bb - 256; ntx = 16; }
        else if (bb < 640) { src = W2;  K = 512; Ncol = 240; rowOff = 0;   dst = BT + OFF2; tile = bb - 512; ntx = 8;  }
        else               { src = Wso; K = 512; Ncol = 40;  rowOff = 240; dst = BT + OFF2; tile = bb - 640; ntx = 2;  }
        int kb = (tile / ntx) * 32, nb = (tile % ntx) * 32;
        int tx = tid & 31, ty = tid >> 5;
        #pragma unroll
        for (int j = ty; j < 32; j += 8) {
            int k = kb + j, n = nb + tx;
            t[j][tx] = (k < K && n < Ncol) ? src[(size_t)k * Ncol + n] : 0.f;
        }
        __syncthreads();
        #pragma unroll
        for (int j = ty; j < 32; j += 8) {
            int n = nb + j, k = kb + tx;
            if (n < Ncol && k < K)
                dst[(size_t)(n + rowOff) * K + k] = __float2half(t[tx][j]);
        }
    } else if (b < 2208 + splitBlk) {
        int i = (b - 2208) * 256 + tid;
        if (i < Nx) AH[i] = __float2half(x[i]);
    } else {
        int e = (b - 2208 - splitBlk) * 256 + tid;
        if (e < E) atomicAdd(&g_deg[edge_at(ei, (long long)E + e)], 1);
    }
}

// ---------------- single-pass fp16 tensor-core GEMM, 3-stage pipeline ----------------
#define GBM 128
#define GBN 64
#define GBK 32
#define APADB 80
#define ABYTES (GBM*APADB)
#define BBYTES (GBN*APADB)
#define STAGEB (ABYTES + BBYTES)          // 15360
#define NSTAGE 3
#define SMEM_GEMM (NSTAGE*STAGEB)         // 46080

__device__ __forceinline__ void cp16(uint32_t dst, const void* src) {
    asm volatile("cp.async.cg.shared.global [%0], [%1], 16;\n" :: "r"(dst), "l"(src));
}

__device__ __forceinline__ void ldsm4(uint32_t* r, uint32_t addr) {
    asm volatile("ldmatrix.sync.aligned.m8n8.x4.shared.b16 {%0,%1,%2,%3}, [%4];"
                 : "=r"(r[0]), "=r"(r[1]), "=r"(r[2]), "=r"(r[3]) : "r"(addr));
}

__device__ __forceinline__ void mma16816(float* c, const uint32_t* a, const uint32_t* b) {
    asm volatile("mma.sync.aligned.m16n8k16.row.col.f32.f16.f16.f32 "
                 "{%0,%1,%2,%3}, {%4,%5,%6,%7}, {%8,%9}, {%0,%1,%2,%3};"
                 : "+f"(c[0]), "+f"(c[1]), "+f"(c[2]), "+f"(c[3])
                 : "r"(a[0]), "r"(a[1]), "r"(a[2]), "r"(a[3]), "r"(b[0]), "r"(b[1]));
}

__global__ void __launch_bounds__(256, 2)
gemm_f16(const __half* __restrict__ AH,
         const __half* __restrict__ BT,
         const float* __restrict__ bias2,
         float* __restrict__ C, __half* __restrict__ Ch,
         float* __restrict__ C2,
         float* __restrict__ ASRC, float* __restrict__ ADST,
         int split1, int split2, int Hatt,
         int M, int K, int Ntot) {
    extern __shared__ char smem[];
    uint32_t sbase = (uint32_t)__cvta_generic_to_shared(smem);
    int tid = threadIdx.x, lane = tid & 31, warp = tid >> 5;
    int bm = blockIdx.y * GBM, bn = blockIdx.x * GBN;
    int m0 = (warp >> 1) * 32, n0 = (warp & 1) * 32;
    int nIter = K / GBK;

    float acc[2][4][4] = {};

    auto stage_load = [&](int it, int s) {
        int k0 = it * GBK;
        uint32_t sb = sbase + s * STAGEB;
        #pragma unroll
        for (int rep = 0; rep < 2; rep++) {
            int idx = tid + rep * 256;
            int r = idx >> 2, ch = idx & 3;
            int ra = bm + r; if (ra >= M) ra = M - 1;
            size_t off = (size_t)ra * K + k0 + ch * 8;
            cp16(sb + r * APADB + ch * 16, AH + off);
        }
        {
            int r = tid >> 2, ch = tid & 3;
            int ra = bn + r; if (ra >= Ntot) ra = Ntot - 1;
            size_t off = (size_t)ra * K + k0 + ch * 8;
            cp16(sb + ABYTES + r * APADB + ch * 16, BT + off);
        }
    };

    int aRow = lane & 15;
    int aKby = (lane >> 4) * 16;
    int bRow = (lane & 7) + ((lane >> 4) << 3);
    int bKby = ((lane >> 3) & 1) * 16;

    stage_load(0, 0);
    asm volatile("cp.async.commit_group;\n");
    if (nIter > 1) stage_load(1, 1);
    asm volatile("cp.async.commit_group;\n");

    for (int it = 0; it < nIter; it++) {
        int s = it % NSTAGE;
        asm volatile("cp.async.wait_group 1;\n");
        __syncthreads();
        if (it + 2 < nIter) stage_load(it + 2, (it + 2) % NSTAGE);
        asm volatile("cp.async.commit_group;\n");

        uint32_t sb  = sbase + s * STAGEB;
        uint32_t pA  = sb + (m0 + aRow) * APADB + aKby;
        uint32_t pB  = sb + ABYTES + (n0 + bRow) * APADB + bKby;

        #pragma unroll
        for (int ks = 0; ks < 2; ks++) {
            int kb = ks * 32;
            uint32_t ah[2][4];
            ldsm4(ah[0], pA + kb);
            ldsm4(ah[1], pA + 16 * APADB + kb);
            uint32_t b01[4], b23[4];
            ldsm4(b01, pB + kb);
            ldsm4(b23, pB + 16 * APADB + kb);
            const uint32_t* bf[4] = {b01, b01 + 2, b23, b23 + 2};
            #pragma unroll
            for (int mt = 0; mt < 2; mt++)
                #pragma unroll
                for (int nt = 0; nt < 4; nt++) mma16816(acc[mt][nt], ah[mt], bf[nt]);
        }
        __syncthreads();
    }

    int attEnd = split2 + 2 * Hatt;
    #pragma unroll
    for (int mt = 0; mt < 2; mt++) {
        #pragma unroll
        for (int nt = 0; nt < 4; nt++) {
            int r = bm + m0 + mt * 16 + (lane >> 2);
            int c = bn + n0 + nt * 8 + (lane & 3) * 2;   // even
            #pragma unroll
            for (int half = 0; half < 2; half++) {
                int rr = r + half * 8;
                if (rr >= M) continue;
                float v0 = acc[mt][nt][half * 2 + 0];
                float v1 = acc[mt][nt][half * 2 + 1];
                if (c < split1) {
                    C[(size_t)rr * split1 + c]     = v0;
                    C[(size_t)rr * split1 + c + 1] = v1;
                    *(__half2*)(Ch + (size_t)rr * split1 + c) =
                        __halves2half2(__float2half(v0), __float2half(v1));
                } else {
                    #pragma unroll
                    for (int j = 0; j < 2; j++) {
                        int cc = c + j;
                        float v = j ? v1 : v0;
                        if (cc < split2) {
                            int c2 = cc - split1;
                            if (bias2) v += bias2[c2];
                            C2[(size_t)rr * (split2 - split1) + c2] = v;
                        } else if (cc < attEnd) {
                            int ca = cc - split2;
                            int h = ca >> 1;
                            ((ca & 1) ? ADST : ASRC)[(size_t)rr * Hatt + h] = v;
                        }
                    }
                }
            }
        }
    }
}

__device__ __forceinline__ float lrelu(float x) { return x > 0.f ? x : NEG_SLOPE * x; }
__device__ __forceinline__ float eluf(float x)  { return x > 0.f ? x : expm1f(x); }

#define H2FMA(u, w, a0, a1) { \
    float2 _f = __half22float2(*(const __half2*)&(u)); \
    (a0) = fmaf((w), _f.x, (a0)); (a1) = fmaf((w), _f.y, (a1)); }

// ---------------- GAT aggregation: warp per node, fp16 payload, coalesced ----------------
__global__ void gat_agg_concat4(const __half* __restrict__ xwh,
                                const float* __restrict__ asrc, const float* __restrict__ adst,
                                const float* __restrict__ bias, const float* __restrict__ skip,
                                float* __restrict__ out, __half* __restrict__ oh,
                                int N) {
    int n = (blockIdx.x * blockDim.x + threadIdx.x) >> 5;
    if (n >= N) return;
    int lane = threadIdx.x & 31;
    int hsel = lane >> 4;
    int s0 = g_rowptr[n], s1 = g_rowptr[n + 1];
    float4 ad = *(const float4*)(adst + n * 4);

    float4 m = make_float4(-1e30f, -1e30f, -1e30f, -1e30f);
    for (int i = s0 + lane; i < s1; i += 32) {
        int s = g_csrsrc[i];
        float4 as = *(const float4*)(asrc + s * 4);
        m.x = fmaxf(m.x, lrelu(as.x + ad.x));
        m.y = fmaxf(m.y, lrelu(as.y + ad.y));
        m.z = fmaxf(m.z, lrelu(as.z + ad.z));
        m.w = fmaxf(m.w, lrelu(as.w + ad.w));
    }
    #pragma unroll
    for (int o = 16; o; o >>= 1) {
        m.x = fmaxf(m.x, __shfl_xor_sync(0xFFFFFFFFu, m.x, o));
        m.y = fmaxf(m.y, __shfl_xor_sync(0xFFFFFFFFu, m.y, o));
        m.z = fmaxf(m.z, __shfl_xor_sync(0xFFFFFFFFu, m.z, o));
        m.w = fmaxf(m.w, __shfl_xor_sync(0xFFFFFFFFu, m.w, o));
    }

    float accA[8] = {}, accB[8] = {};
    float4 den = {0,0,0,0};

    float4 asC = {0,0,0,0}; uint4 Ac = {0,0,0,0}, Bc = {0,0,0,0};
    if (s0 < s1) {
        int s = g_csrsrc[s0];
        asC = *(const float4*)(asrc + s * 4);
        const uint4* row = (const uint4*)(xwh + (size_t)s * HIDDIM);
        Ac = row[lane]; Bc = row[32 + lane];
    }
    for (int i = s0; i < s1; i++) {
        float4 asN = {0,0,0,0}; uint4 An = {0,0,0,0}, Bn = {0,0,0,0};
        if (i + 1 < s1) {
            int s = g_csrsrc[i + 1];
            asN = *(const float4*)(asrc + s * 4);
            const uint4* row = (const uint4*)(xwh + (size_t)s * HIDDIM);
            An = row[lane]; Bn = row[32 + lane];
        }
        float w0 = __expf(lrelu(asC.x + ad.x) - m.x);
        float w1 = __expf(lrelu(asC.y + ad.y) - m.y);
        float w2 = __expf(lrelu(asC.z + ad.z) - m.z);
        float w3 = __expf(lrelu(asC.w + ad.w) - m.w);
        den.x += w0; den.y += w1; den.z += w2; den.w += w3;
        float wa = hsel ? w1 : w0;
        float wb = hsel ? w3 : w2;
        H2FMA(Ac.x, wa, accA[0], accA[1]);
        H2FMA(Ac.y, wa, accA[2], accA[3]);
        H2FMA(Ac.z, wa, accA[4], accA[5]);
        H2FMA(Ac.w, wa, accA[6], accA[7]);
        H2FMA(Bc.x, wb, accB[0], accB[1]);
        H2FMA(Bc.y, wb, accB[2], accB[3]);
        H2FMA(Bc.z, wb, accB[4], accB[5]);
        H2FMA(Bc.w, wb, accB[6], accB[7]);
        asC = asN; Ac = An; Bc = Bn;
    }
    float invs[4];
    invs[0] = 1.f / (den.x + 1e-16f); invs[1] = 1.f / (den.y + 1e-16f);
    invs[2] = 1.f / (den.z + 1e-16f); invs[3] = 1.f / (den.w + 1e-16f);
    float invA = invs[hsel], invB = invs[2 + hsel];

    #pragma unroll
    for (int g = 0; g < 2; g++) {
        const float* acc = g ? accB : accA;
        float inv = g ? invB : invA;
        int ch = g * 256 + lane * 8;
        int base = n * HIDDIM + ch;
        #pragma unroll
        for (int q = 0; q < 2; q++) {
            float4 bv = *(const float4*)(bias + ch + q * 4);
            float4 sv = *(const float4*)(skip + base + q * 4);
            float4 o;
            o.x = eluf(acc[q*4+0] * inv + bv.x + sv.x);
            o.y = eluf(acc[q*4+1] * inv + bv.y + sv.y);
            o.z = eluf(acc[q*4+2] * inv + bv.z + sv.z);
            o.w = eluf(acc[q*4+3] * inv + bv.w + sv.w);
            *(float4*)(out + base + q * 4) = o;
            *(__half2*)(oh + base + q * 4)     = __halves2half2(__float2half(o.x), __float2half(o.y));
            *(__half2*)(oh + base + q * 4 + 2) = __halves2half2(__float2half(o.z), __float2half(o.w));
        }
    }
}

// ---------------- final layer: warp per node, fp16 payload, one coalesced uint4/edge ----------------
__global__ void gat_agg_mean6(const __half* __restrict__ xwh,
                              const float* __restrict__ asrc, const float* __restrict__ adst,
                              float* __restrict__ out, int N) {
    int n = (blockIdx.x * blockDim.x + threadIdx.x) >> 5;
    if (n >= N) return;
    int lane = threadIdx.x & 31;
    bool act = lane < 30;
    int h = act ? (lane / 5) : 5;
    int s0 = g_rowptr[n], s1 = g_rowptr[n + 1];

    float mloc = -1e30f;
    int h2 = act ? (lane % 6) : 0;
    float ad2 = adst[n * NHEADL + h2];
    if (act) {
        for (int i = s0 + lane / 6; i < s1; i += 5) {
            int s = g_csrsrc[i];
            mloc = fmaxf(mloc, lrelu(asrc[s * NHEADL + h2] + ad2));
        }
    }
    #pragma unroll
    for (int off = 6; off <= 24; off <<= 1) {
        int src = lane + off; if (src >= 30) src -= 30;
        float t = __shfl_sync(0xFFFFFFFFu, mloc, src);
        mloc = fmaxf(mloc, t);
    }
    float m  = __shfl_sync(0xFFFFFFFFu, mloc, h);
    float ad = adst[n * NHEADL + h];

    float4 acc0 = {0,0,0,0}, acc1 = {0,0,0,0};
    float den = 0.f;

    float aC = 0.f; uint4 Vc = {0,0,0,0};
    if (s0 < s1) {
        int s = g_csrsrc[s0];
        aC = asrc[s * NHEADL + h];
        if (act) Vc = *(const uint4*)(xwh + (size_t)s * (NHEADL * NCLASS) + lane * 8);
    }
    for (int i = s0; i < s1; i++) {
        float aN = 0.f; uint4 Vn = {0,0,0,0};
        if (i + 1 < s1) {
            int s = g_csrsrc[i + 1];
            aN = asrc[s * NHEADL + h];
            if (act) Vn = *(const uint4*)(xwh + (size_t)s * (NHEADL * NCLASS) + lane * 8);
        }
        float w = __expf(lrelu(aC + ad) - m);
        den += w;
        H2FMA(Vc.x, w, acc0.x, acc0.y);
        H2FMA(Vc.y, w, acc0.z, acc0.w);
        H2FMA(Vc.z, w, acc1.x, acc1.y);
        H2FMA(Vc.w, w, acc1.z, acc1.w);
        aC = aN; Vc = Vn;
    }
    float sc = act ? (1.f / (den + 1e-16f)) * (1.f / (float)NHEADL) : 0.f;
    acc0.x *= sc; acc0.y *= sc; acc0.z *= sc; acc0.w *= sc;
    acc1.x *= sc; acc1.y *= sc; acc1.z *= sc; acc1.w *= sc;

    #define SHF4(d, v, src) \
        d.x = __shfl_sync(0xFFFFFFFFu, v.x, src); \
        d.y = __shfl_sync(0xFFFFFFFFu, v.y, src); \
        d.z = __shfl_sync(0xFFFFFFFFu, v.z, src); \
        d.w = __shfl_sync(0xFFFFFFFFu, v.w, src);
    float4 t;
    SHF4(t, acc0, (lane + 15) & 31);
    acc0.x += t.x; acc0.y += t.y; acc0.z += t.z; acc0.w += t.w;
    SHF4(t, acc1, (lane + 15) & 31);
    acc1.x += t.x; acc1.y += t.y; acc1.z += t.z; acc1.w += t.w;
    float4 a5, a10, b5, b10;
    SHF4(a5,  acc0, (lane + 5) & 31);
    SHF4(a10, acc0, (lane + 10) & 31);
    SHF4(b5,  acc1, (lane + 5) & 31);
    SHF4(b10, acc1, (lane + 10) & 31);
    if (lane < 5) {
        float4* o = (float4*)(out + (size_t)n * NCLASS + lane * 8);
        float4 c0 = o[0];
        float4 c1 = o[1];
        c0.x += acc0.x + a5.x + a10.x; c0.y += acc0.y + a5.y + a10.y;
        c0.z += acc0.z + a5.z + a10.z; c0.w += acc0.w + a5.w + a10.w;
        c1.x += acc1.x + b5.x + b10.x; c1.y += acc1.y + b5.y + b10.y;
        c1.z += acc1.z + b5.z + b10.z; c1.w += acc1.w + b5.w + b10.w;
        o[0] = c0;
        o[1] = c1;
    }
    #undef SHF4
}

// ---------------- launch ----------------
extern "C" void kernel_launch(void* const* d_in, const int* in_sizes, int n_in,
                              void* d_out, int out_size) {
    const float* x        = (const float*)d_in[0];
    const void*  ei       = d_in[1];
    const float* W0       = (const float*)d_in[2];
    const float* a_src0   = (const float*)d_in[3];
    const float* a_dst0   = (const float*)d_in[4];
    const float* b0       = (const float*)d_in[5];
    const float* Wskip_in = (const float*)d_in[6];
    const float* W1       = (const float*)d_in[7];
    const float* a_src1   = (const float*)d_in[8];
    const float* a_dst1   = (const float*)d_in[9];
    const float* b1       = (const float*)d_in[10];
    const float* W2       = (const float*)d_in[11];
    const float* a_src2   = (const float*)d_in[12];
    const float* a_dst2   = (const float*)d_in[13];
    const float* b2       = (const float*)d_in[14];
    const float* Wskip_out= (const float*)d_in[15];
    float* out = (float*)d_out;

    int N = in_sizes[0] / NFEAT;
    int E = in_sizes[1] / 2;

    float *XW, *X1, *X2, *SKIP, *ASRC, *ADST;
    __half *AH, *XWH, *BT;
    int *deg;
    cudaGetSymbolAddress((void**)&XW,   g_XW);
    cudaGetSymbolAddress((void**)&X1,   g_X1);
    cudaGetSymbolAddress((void**)&X2,   g_X2);
    cudaGetSymbolAddress((void**)&SKIP, g_SKIP);
    cudaGetSymbolAddress((void**)&ASRC, g_ASRC);
    cudaGetSymbolAddress((void**)&ADST, g_ADST);
    cudaGetSymbolAddress((void**)&AH,   g_AH);
    cudaGetSymbolAddress((void**)&XWH,  g_XWH);
    cudaGetSymbolAddress((void**)&BT,   g_BT);
    cudaGetSymbolAddress((void**)&deg,  g_deg);

    cudaFuncSetAttribute(gemm_f16, cudaFuncAttributeMaxDynamicSharedMemorySize, SMEM_GEMM);

    cudaMemsetAsync(deg, 0, 2 * MAXN * sizeof(int));
    detect_i64_kernel<<<1, 32>>>((const int*)ei);

    dim3 blk(256);
    auto cdiv = [](int a, int b) { return (a + b - 1) / b; };
    auto ggrid = [&](int Ncol) { return dim3(cdiv(Ncol, GBN), cdiv(N, GBM)); };

    int gridN = cdiv(N * 32, 256);
    int Nx = N * NFEAT;
    int splitBlk = cdiv(Nx, 256);

    // ---- fused preprocessing ----
    prep_kernel<<<2208 + splitBlk + cdiv(E, 256), blk>>>(
        x, Nx, splitBlk, ei, E, W0, Wskip_in, W1, W2, Wskip_out,
        a_src0, a_dst0, a_src1, a_dst1, a_src2, a_dst2,
        AH, BT);

    // ---- fork: CSR build on side stream, overlapped with GEMM0 ----
    cudaStream_t s2;
    cudaStreamCreateWithFlags(&s2, cudaStreamNonBlocking);
    cudaEvent_t evPrep, evCSR;
    cudaEventCreateWithFlags(&evPrep, cudaEventDisableTiming);
    cudaEventCreateWithFlags(&evCSR,  cudaEventDisableTiming);

    cudaEventRecord(evPrep, 0);
    cudaStreamWaitEvent(s2, evPrep, 0);
    scan_kernel<<<1, 1024, 0, s2>>>(N);
    scatter_kernel<<<cdiv(E, 256), blk, 0, s2>>>(ei, E);
    cudaEventRecord(evCSR, s2);

    // ---- layer 0 GEMM ----
    gemm_f16<<<ggrid(1032), blk, SMEM_GEMM>>>(
        AH, BT + OFF0, nullptr, XW, XWH, SKIP, ASRC, ADST,
        HIDDIM, 2 * HIDDIM, NHEAD, N, NFEAT, 1032);

    cudaStreamWaitEvent(0, evCSR, 0);
    gat_agg_concat4<<<gridN, blk>>>(XWH, ASRC, ADST, b0, SKIP, X1, AH, N);

    // ---- layer 1 ----
    gemm_f16<<<ggrid(520), blk, SMEM_GEMM>>>(
        AH, BT + OFF1, nullptr, XW, XWH, XW, ASRC, ADST,
        HIDDIM, HIDDIM, NHEAD, N, HIDDIM, 520);
    gat_agg_concat4<<<gridN, blk>>>(XWH, ASRC, ADST, b1, X1, X2, AH, N);

    // ---- layer 2 ----
    gemm_f16<<<ggrid(292), blk, SMEM_GEMM>>>(
        AH, BT + OFF2, b2, XW, XWH, out, ASRC, ADST,
        NHEADL * NCLASS, NHEADL * NCLASS + NCLASS, NHEADL, N, HIDDIM, 292);
    gat_agg_mean6<<<gridN, blk>>>(XWH, ASRC, ADST, out, N);

    cudaEventDestroy(evPrep);
    cudaEventDestroy(evCSR);
    cudaStreamDestroy(s2);
}